// round 15
// baseline (speedup 1.0000x reference)
#include <cuda_runtime.h>
#include <cuda_fp16.h>
#include <math.h>

#define Z 2
#define NPT 256
#define CH 16
#define HEADS 2
#define NB 10
#define HD 100
#define NBV 3
#define K1STR 102
#define NTAB 2048
#define DMAX 8.7f
#define STEP10 (5.0f / 9.0f)
#define INV10 (9.0f / 5.0f)
#define NSLOT 8
#define ZNC (Z * NPT * CH)
#define ASTRIDE 120
#define BSTRIDE 24
#define KPAD 112
#define VSTR 112

typedef unsigned long long u64t;
typedef unsigned int uint32;

// ---------------- scratch ----------------
__device__ float g_q[HEADS * Z * NPT * CH];
__device__ float g_WfF[HEADS * Z * NPT * HD * CH];   // fp32 (score path) [h][z][b][i][m]
__device__ __half g_VfF[HEADS * Z * NPT * HD * CH];  // fp16 (value path)
__device__ float g_scores[HEADS * Z * NPT * NPT];    // [h][z][a][b]
__device__ float g_p[HEADS * Z * NPT * NPT];         // [h][z][b][a]
__device__ float g_aopart[NSLOT * ZNC];
__device__ float g_outpart[NSLOT * ZNC];
__device__ float  g_Ktab[HEADS * NTAB * HD];         // fp32 (score path)
__device__ __align__(16) __half g_Ctab[NTAB * VSTR];
__device__ __align__(16) __half g_Vtab[HEADS * NTAB * VSTR];

__device__ __forceinline__ float swishf(float x) {
    return x / (1.0f + __expf(-x));
}
__device__ __forceinline__ void fma2(u64t& d, u64t a, u64t b) {
    asm("fma.rn.f32x2 %0, %1, %2, %0;" : "+l"(d) : "l"(a), "l"(b));
}
__device__ __forceinline__ float up2sum(u64t v) {
    float2 f;
    asm("mov.b64 {%0, %1}, %2;" : "=f"(f.x), "=f"(f.y) : "l"(v));
    return f.x + f.y;
}
__device__ __forceinline__ u64t lds64(const float* p) {
    return *(const u64t*)p;
}
__device__ __forceinline__ void ldsm_x4(uint32& r0, uint32& r1, uint32& r2, uint32& r3,
                                        uint32 addr) {
    asm volatile("ldmatrix.sync.aligned.m8n8.x4.shared.b16 {%0,%1,%2,%3}, [%4];"
                 : "=r"(r0), "=r"(r1), "=r"(r2), "=r"(r3) : "r"(addr));
}
__device__ __forceinline__ void ldsm_x2t(uint32& r0, uint32& r1, uint32 addr) {
    asm volatile("ldmatrix.sync.aligned.m8n8.x2.trans.shared.b16 {%0,%1}, [%2];"
                 : "=r"(r0), "=r"(r1) : "r"(addr));
}
__device__ __forceinline__ void mma16816(float* d, uint32 a0, uint32 a1, uint32 a2,
                                         uint32 a3, uint32 b0, uint32 b1) {
    asm volatile("mma.sync.aligned.m16n8k16.row.col.f32.f16.f16.f32 "
                 "{%0,%1,%2,%3},{%4,%5,%6,%7},{%8,%9},{%0,%1,%2,%3};"
                 : "+f"(d[0]), "+f"(d[1]), "+f"(d[2]), "+f"(d[3])
                 : "r"(a0), "r"(a1), "r"(a2), "r"(a3), "r"(b0), "r"(b1));
}
// 8-half lerp: (r0, r1, frac) -> packed uint4 of fp16
__device__ __forceinline__ uint4 lerp8h(uint4 r0, uint4 r1, float f) {
    float2 a0 = __half22float2(*(__half2*)&r0.x);
    float2 a1 = __half22float2(*(__half2*)&r0.y);
    float2 a2 = __half22float2(*(__half2*)&r0.z);
    float2 a3 = __half22float2(*(__half2*)&r0.w);
    float2 b0 = __half22float2(*(__half2*)&r1.x);
    float2 b1 = __half22float2(*(__half2*)&r1.y);
    float2 b2 = __half22float2(*(__half2*)&r1.z);
    float2 b3 = __half22float2(*(__half2*)&r1.w);
    float2 o0, o1, o2, o3;
    o0.x = fmaf(f, b0.x - a0.x, a0.x); o0.y = fmaf(f, b0.y - a0.y, a0.y);
    o1.x = fmaf(f, b1.x - a1.x, a1.x); o1.y = fmaf(f, b1.y - a1.y, a1.y);
    o2.x = fmaf(f, b2.x - a2.x, a2.x); o2.y = fmaf(f, b2.y - a2.y, a2.y);
    o3.x = fmaf(f, b3.x - a3.x, a3.x); o3.y = fmaf(f, b3.y - a3.y, a3.y);
    __half2 h0 = __float22half2_rn(o0);
    __half2 h1 = __float22half2_rn(o1);
    __half2 h2 = __float22half2_rn(o2);
    __half2 h3 = __float22half2_rn(o3);
    uint4 st;
    st.x = *(uint32*)&h0; st.y = *(uint32*)&h1;
    st.z = *(uint32*)&h2; st.w = *(uint32*)&h3;
    return st;
}

// ---------------- Kernel B: all prep fused (tables + Vtab + proj) ----------------
#define B_SMEM_FLOATS 18240
__global__ __launch_bounds__(256) void build_kernel(const float* __restrict__ features,
                                                    const float* __restrict__ Wq,
                                                    const float* __restrict__ Kf,
                                                    const float* __restrict__ Vf,
                                                    const float* __restrict__ K0,
                                                    const float* __restrict__ K1,
                                                    const float* __restrict__ C0,
                                                    const float* __restrict__ C1,
                                                    const float* __restrict__ V0) {
    extern __shared__ float sm[];
    const int bx = blockIdx.x;
    const int tid = threadIdx.x;

    if (bx < 96) {
        float* s_k0T = sm;            // 1000
        float* s_k1T = sm + 1000;     // 10200
        float* s_bas = sm + 11200;    // 640
        float* s_h1  = sm + 11840;    // 6400
        const int net = bx / 32;
        const int p0 = (bx % 32) * 64;
        const float* K0src = (net < 2) ? (K0 + net * NB * HD) : C0;
        const float* K1src = (net < 2) ? (K1 + net * HD * HD) : C1;

        for (int e = tid; e < NB * HD; e += 256) {
            int n = e / HD, m = e - n * HD;
            s_k0T[m * NB + n] = K0src[e];
        }
        for (int e = tid; e < HD * HD; e += 256) {
            int n = e / HD, m = e - n * HD;
            s_k1T[m * K1STR + n] = K1src[e];
        }
        const float DELTA = DMAX / (float)(NTAB - 1);
        for (int e = tid; e < 64 * NB; e += 256) {
            int p = e / NB, n = e - p * NB;
            float d = (float)(p0 + p) * DELTA;
            float diff = (d - n * STEP10) * INV10;
            s_bas[e] = (fabsf(diff) < 1.0f) ? cospif(0.5f * diff) : 0.0f;
        }
        __syncthreads();

        {
            const int p = tid >> 2, q4 = tid & 3;
            const float* bp = s_bas + p * NB;
            u64t bb0 = lds64(bp), bb1 = lds64(bp + 2), bb2 = lds64(bp + 4),
                 bb3 = lds64(bp + 6), bb4 = lds64(bp + 8);
#pragma unroll 5
            for (int mm = 0; mm < 25; mm++) {
                int m = q4 * 25 + mm;
                const float* kp = s_k0T + m * NB;
                u64t acc = 0ull;
                fma2(acc, bb0, lds64(kp));
                fma2(acc, bb1, lds64(kp + 2));
                fma2(acc, bb2, lds64(kp + 4));
                fma2(acc, bb3, lds64(kp + 6));
                fma2(acc, bb4, lds64(kp + 8));
                s_h1[p * HD + m] = swishf(up2sum(acc));
            }
        }
        __syncthreads();

        {
            const int ty = tid >> 4, tx = tid & 15;
            const float* hbase = s_h1 + ty * 4 * HD;
            const bool tail = tx < 4;
            u64t acc[4][7];
#pragma unroll
            for (int r = 0; r < 4; r++)
#pragma unroll
                for (int j = 0; j < 7; j++) acc[r][j] = 0ull;
#pragma unroll 2
            for (int t = 0; t < 50; t++) {
                u64t h0 = lds64(hbase + 2 * t);
                u64t h1v = lds64(hbase + HD + 2 * t);
                u64t h2v = lds64(hbase + 2 * HD + 2 * t);
                u64t h3v = lds64(hbase + 3 * HD + 2 * t);
#pragma unroll
                for (int j = 0; j < 6; j++) {
                    u64t kv = lds64(s_k1T + (tx + 16 * j) * K1STR + 2 * t);
                    fma2(acc[0][j], h0, kv);
                    fma2(acc[1][j], h1v, kv);
                    fma2(acc[2][j], h2v, kv);
                    fma2(acc[3][j], h3v, kv);
                }
                if (tail) {
                    u64t kv = lds64(s_k1T + (tx + 96) * K1STR + 2 * t);
                    fma2(acc[0][6], h0, kv);
                    fma2(acc[1][6], h1v, kv);
                    fma2(acc[2][6], h2v, kv);
                    fma2(acc[3][6], h3v, kv);
                }
            }
            if (net < 2) {
                float* tabf = g_Ktab + (size_t)net * NTAB * HD;
#pragma unroll
                for (int r = 0; r < 4; r++) {
                    float* row = tabf + (size_t)(p0 + ty * 4 + r) * HD;
#pragma unroll
                    for (int j = 0; j < 6; j++)
                        row[tx + 16 * j] = swishf(up2sum(acc[r][j]));
                    if (tail)
                        row[tx + 96] = swishf(up2sum(acc[r][6]));
                }
            } else {
#pragma unroll
                for (int r = 0; r < 4; r++) {
                    __half* row = g_Ctab + (size_t)(p0 + ty * 4 + r) * VSTR;
#pragma unroll
                    for (int j = 0; j < 6; j++)
                        row[tx + 16 * j] = __float2half(swishf(up2sum(acc[r][j])));
                    if (tail)
                        row[tx + 96] = __float2half(swishf(up2sum(acc[r][6])));
                    else
                        row[96 + tx] = __half(0);
                }
            }
        }
    } else if (bx < 160) {
        const int t = bx - 96;
        const int h = t >> 5;
        const int p0 = (t & 31) * 64;
        const int p = tid >> 2, q = tid & 3;
        const float DELTA = DMAX / (float)(NTAB - 1);
        float d = (float)(p0 + p) * DELTA;
        float bas[NBV];
#pragma unroll
        for (int n = 0; n < NBV; n++) {
            float diff = (d - n * 2.5f) * 0.4f;
            bas[n] = (fabsf(diff) < 1.0f) ? cospif(0.5f * diff) : 0.0f;
        }
        const float* v = V0 + h * NBV * HD;
        __half* row = g_Vtab + (size_t)h * NTAB * VSTR + (size_t)(p0 + p) * VSTR;
#pragma unroll 5
        for (int u = 0; u < 25; u++) {
            int m = q * 25 + u;
            float acc = bas[0] * v[m] + bas[1] * v[HD + m] + bas[2] * v[2 * HD + m];
            row[m] = __float2half(swishf(acc));
        }
        if (q == 3) {
            *(uint2*)(row + 100) = make_uint2(0u, 0u);
            *(uint2*)(row + 104) = make_uint2(0u, 0u);
            *(uint2*)(row + 108) = make_uint2(0u, 0u);
        }
    } else {
        // proj
        float* fs = sm;
        const int t = bx - 160;
        const int zb = t >> 2;
        const int z = zb >> 5;
        const int b0 = (zb & 31) * 8;
        const int sl = t & 3;
        if (tid < 8 * CH) fs[tid] = features[(z * NPT + b0) * CH + tid];
        __syncthreads();

        if (sl == 0) {
            const int bl = tid >> 5, r = tid & 31, h = r >> 4, o = r & 15;
            float acc = 0.f;
#pragma unroll
            for (int i = 0; i < CH; i++) acc += fs[bl * CH + i] * Wq[(h * CH + o) * CH + i];
            g_q[((h * Z + z) * NPT + b0 + bl) * CH + o] = acc;
        }

        for (int e = tid; e < HEADS * 25 * CH; e += 256) {
            const int h = e / 400;
            const int rr = e - h * 400;
            const int i = rr / 25, mm = rr - i * 25;
            const int m = sl * 25 + mm;
            const int r = i * HD + m;
            const float* kfp = Kf + (h * HD + m) * (CH * CH) + i * CH;
            const float* vfp = Vf + (h * HD + m) * (CH * CH) + i * CH;
            float4 k0 = *(const float4*)(kfp);
            float4 k1 = *(const float4*)(kfp + 4);
            float4 k2 = *(const float4*)(kfp + 8);
            float4 k3 = *(const float4*)(kfp + 12);
            float4 v0 = *(const float4*)(vfp);
            float4 v1 = *(const float4*)(vfp + 4);
            float4 v2 = *(const float4*)(vfp + 8);
            float4 v3 = *(const float4*)(vfp + 12);
#pragma unroll
            for (int bl = 0; bl < 8; bl++) {
                const float* f = fs + bl * CH;
                float aK = k0.x*f[0]+k0.y*f[1]+k0.z*f[2]+k0.w*f[3]
                         + k1.x*f[4]+k1.y*f[5]+k1.z*f[6]+k1.w*f[7]
                         + k2.x*f[8]+k2.y*f[9]+k2.z*f[10]+k2.w*f[11]
                         + k3.x*f[12]+k3.y*f[13]+k3.z*f[14]+k3.w*f[15];
                float aV = v0.x*f[0]+v0.y*f[1]+v0.z*f[2]+v0.w*f[3]
                         + v1.x*f[4]+v1.y*f[5]+v1.z*f[6]+v1.w*f[7]
                         + v2.x*f[8]+v2.y*f[9]+v2.z*f[10]+v2.w*f[11]
                         + v3.x*f[12]+v3.y*f[13]+v3.z*f[14]+v3.w*f[15];
                int o = ((h * Z + z) * NPT + b0 + bl) * (HD * CH) + r;
                g_WfF[o] = aK;
                g_VfF[o] = __float2half(aV);
            }
        }
    }
}

// ---------------- Kernel P: scores via split-fp16 MMA (fp32-accurate) ----------------
__global__ __launch_bounds__(256, 4) void pair_kernel(const float* __restrict__ xyz) {
    __shared__ __align__(16) __half s_Ah[64 * ASTRIDE];
    __shared__ __align__(16) __half s_Al[64 * ASTRIDE];
    __shared__ __align__(16) __half s_Bh[KPAD * BSTRIDE];
    __shared__ __align__(16) __half s_Bl[KPAD * BSTRIDE];
    __shared__ float s_d[256];
    __shared__ float s_red[64];

    const int tid = threadIdx.x;
    const int b = blockIdx.x;
    const int z = blockIdx.y >> 1;
    const int h = blockIdx.y & 1;

    {
        const float* src = g_WfF + ((size_t)((h * Z + z) * NPT + b)) * (HD * CH);
        for (int e = tid; e < KPAD * CH; e += 256) {
            int k = e >> 4, i = e & 15;
            float w = (k < HD) ? src[i * HD + k] : 0.0f;
            __half hh = __float2half_rn(w);
            s_Bh[k * BSTRIDE + i] = hh;
            s_Bl[k * BSTRIDE + i] = __float2half_rn(w - __half2float(hh));
        }
    }
    {
        float bx = xyz[(z * NPT + b) * 3 + 0];
        float by = xyz[(z * NPT + b) * 3 + 1];
        float bz = xyz[(z * NPT + b) * 3 + 2];
        float dx = bx - xyz[(z * NPT + tid) * 3 + 0];
        float dy = by - xyz[(z * NPT + tid) * 3 + 1];
        float dz = bz - xyz[(z * NPT + tid) * 3 + 2];
        s_d[tid] = sqrtf(dx * dx + dy * dy + dz * dz + 1e-12f);
    }
    if (tid < 192) {
        int row = tid / 3, off = 100 + 4 * (tid % 3);
        *(uint2*)(s_Ah + row * ASTRIDE + off) = make_uint2(0u, 0u);
        *(uint2*)(s_Al + row * ASTRIDE + off) = make_uint2(0u, 0u);
    }
    __syncthreads();

    const int w = tid >> 5, l = tid & 31;
    const int rt = w >> 1, nt = w & 1;
    uint32 sAh = (uint32)__cvta_generic_to_shared(s_Ah);
    uint32 sAl = (uint32)__cvta_generic_to_shared(s_Al);
    uint32 sBh = (uint32)__cvta_generic_to_shared(s_Bh);
    uint32 sBl = (uint32)__cvta_generic_to_shared(s_Bl);

    for (int ch = 0; ch < 4; ch++) {
        const int ach0 = ch * 64;
        {
            const int p = tid >> 2, q = tid & 3;
            const float TSCALE = (float)(NTAB - 1) / DMAX;
            float x = s_d[ach0 + p] * TSCALE;
            int i0 = (int)x;
            if (i0 > NTAB - 2) i0 = NTAB - 2;
            float f = x - (float)i0;
            const float* kr = g_Ktab + ((size_t)h * NTAB + i0) * HD;
            __half* dh = s_Ah + p * ASTRIDE;
            __half* dl = s_Al + p * ASTRIDE;
            for (int c = q; c < 25; c += 4) {
                float4 a0v = *(const float4*)(kr + 4 * c);
                float4 a1v = *(const float4*)(kr + HD + 4 * c);
                float4 o;
                o.x = fmaf(f, a1v.x - a0v.x, a0v.x);
                o.y = fmaf(f, a1v.y - a0v.y, a0v.y);
                o.z = fmaf(f, a1v.z - a0v.z, a0v.z);
                o.w = fmaf(f, a1v.w - a0v.w, a0v.w);
                __half2 h01 = __float22half2_rn(make_float2(o.x, o.y));
                __half2 h23 = __float22half2_rn(make_float2(o.z, o.w));
                float2 r01 = __half22float2(h01);
                float2 r23 = __half22float2(h23);
                __half2 l01 = __float22half2_rn(make_float2(o.x - r01.x, o.y - r01.y));
                __half2 l23 = __float22half2_rn(make_float2(o.z - r23.x, o.w - r23.y));
                uint2 sth, stl;
                sth.x = *(uint32*)&h01; sth.y = *(uint32*)&h23;
                stl.x = *(uint32*)&l01; stl.y = *(uint32*)&l23;
                *(uint2*)(dh + 4 * c) = sth;
                *(uint2*)(dl + 4 * c) = stl;
            }
        }
        __syncthreads();

        {
            float acc[4] = {0.f, 0.f, 0.f, 0.f};
#pragma unroll
            for (int kt = 0; kt < 7; kt++) {
                uint32 boff = (kt * 16 + (l & 15)) * (BSTRIDE * 2) + nt * 16;
                uint32 bh0, bh1, bl0, bl1;
                ldsm_x2t(bh0, bh1, sBh + boff);
                ldsm_x2t(bl0, bl1, sBl + boff);
                uint32 aoff = (rt * 16 + (l & 15)) * (ASTRIDE * 2)
                            + kt * 32 + (l >> 4) * 16;
                uint32 a0, a1, a2, a3, c0, c1, c2, c3;
                ldsm_x4(a0, a1, a2, a3, sAh + aoff);
                ldsm_x4(c0, c1, c2, c3, sAl + aoff);
                mma16816(acc, a0, a1, a2, a3, bh0, bh1);
                mma16816(acc, a0, a1, a2, a3, bl0, bl1);
                mma16816(acc, c0, c1, c2, c3, bh0, bh1);
            }
            const int rlo = ach0 + rt * 16 + (l >> 2);
            const int rhi = rlo + 8;
            const int col = nt * 8 + 2 * (l & 3);
            const int qbase = ((h * Z + z) * NPT) * CH;
            float2 qlo = *(const float2*)(g_q + qbase + rlo * CH + col);
            float2 qhi = *(const float2*)(g_q + qbase + rhi * CH + col);
            float slo = acc[0] * qlo.x + acc[1] * qlo.y;
            float shi = acc[2] * qhi.x + acc[3] * qhi.y;
            slo += __shfl_xor_sync(0xffffffffu, slo, 1);
            slo += __shfl_xor_sync(0xffffffffu, slo, 2);
            shi += __shfl_xor_sync(0xffffffffu, shi, 1);
            shi += __shfl_xor_sync(0xffffffffu, shi, 2);
            if (nt == 1 && (l & 3) == 0) {
                s_red[rt * 16 + (l >> 2)] = slo;
                s_red[rt * 16 + 8 + (l >> 2)] = shi;
            }
            __syncthreads();
            if (nt == 0 && (l & 3) == 0) {
                const int rowl = rt * 16 + (l >> 2);
                const int rowh = rowl + 8;
                g_scores[((h * Z + z) * NPT + (ach0 + rowl)) * NPT + b] =
                    (slo + s_red[rowl]) * (1.0f / CH);
                g_scores[((h * Z + z) * NPT + (ach0 + rowh)) * NPT + b] =
                    (shi + s_red[rowh]) * (1.0f / CH);
            }
        }
        __syncthreads();
    }
}

// ---------------- Kernel S: softmax -> transposed p; zero aopart + outpart ----------------
__global__ __launch_bounds__(256) void softmax_p_kernel() {
    const int bid = blockIdx.x;
    const int z = bid / NPT, a = bid % NPT;
    const int tid = threadIdx.x;
    const int wid = tid >> 5, lane = tid & 31;
    __shared__ float swr[8];

#pragma unroll
    for (int h = 0; h < HEADS; h++) {
        float sc = g_scores[((h * Z + z) * NPT + a) * NPT + tid];
        float m = sc;
#pragma unroll
        for (int s = 16; s > 0; s >>= 1) m = fmaxf(m, __shfl_xor_sync(0xffffffffu, m, s));
        if (lane == 0) swr[wid] = m;
        __syncthreads();
        float mx = swr[0];
#pragma unroll
        for (int j = 1; j < 8; j++) mx = fmaxf(mx, swr[j]);
        __syncthreads();
        float e = __expf(sc - mx);
        float sum = e;
#pragma unroll
        for (int s = 16; s > 0; s >>= 1) sum += __shfl_xor_sync(0xffffffffu, sum, s);
        if (lane == 0) swr[wid] = sum;
        __syncthreads();
        float tot = swr[0];
#pragma unroll
        for (int j = 1; j < 8; j++) tot += swr[j];
        __syncthreads();
        g_p[((h * Z + z) * NPT + tid) * NPT + a] = e / tot;
    }
    if (tid < 128) g_aopart[bid * 128 + tid] = 0.0f;
    else g_outpart[bid * 128 + (tid - 128)] = 0.0f;
}

// ---------------- Kernel V: value contraction (r13 shape: 16B gathers + mma) ----------------
__global__ __launch_bounds__(256, 4) void val_kernel(const float* __restrict__ xyz) {
    __shared__ __align__(16) __half s_A[64 * ASTRIDE];
    __shared__ __align__(16) __half s_B[KPAD * BSTRIDE];
    __shared__ float s_d[256];
    __shared__ float s_p[256];

    const int tid = threadIdx.x;
    const int b = blockIdx.x;
    const int z = blockIdx.y >> 1;
    const int h = blockIdx.y & 1;
    const int slot = b >> 5;

    {
        const __half* src = g_VfF + ((size_t)((h * Z + z) * NPT + b)) * (HD * CH);
        for (int e = tid; e < KPAD * CH; e += 256) {
            int k = e >> 4, i = e & 15;
            s_B[k * BSTRIDE + i] = (k < HD) ? src[i * HD + k] : __half(0);
        }
    }
    {
        float bx = xyz[(z * NPT + b) * 3 + 0];
        float by = xyz[(z * NPT + b) * 3 + 1];
        float bz = xyz[(z * NPT + b) * 3 + 2];
        float dx = bx - xyz[(z * NPT + tid) * 3 + 0];
        float dy = by - xyz[(z * NPT + tid) * 3 + 1];
        float dz = bz - xyz[(z * NPT + tid) * 3 + 2];
        s_d[tid] = sqrtf(dx * dx + dy * dy + dz * dz + 1e-12f);
        s_p[tid] = g_p[((h * Z + z) * NPT + b) * NPT + tid];
    }
    __syncthreads();

    const int w = tid >> 5, l = tid & 31;
    const int rt = w >> 1, nt = w & 1;
    uint32 sAb = (uint32)__cvta_generic_to_shared(s_A);
    uint32 sBb = (uint32)__cvta_generic_to_shared(s_B);

    for (int ch = 0; ch < 4; ch++) {
        const int ach0 = ch * 64;
        {
            const int p = tid >> 2, q = tid & 3;
            const float TSCALE = (float)(NTAB - 1) / DMAX;
            float x = s_d[ach0 + p] * TSCALE;
            int i0 = (int)x;
            if (i0 > NTAB - 2) i0 = NTAB - 2;
            float f = x - (float)i0;
            const __half* vr = g_Vtab + ((size_t)h * NTAB + i0) * VSTR;
            __half* dst = s_A + p * ASTRIDE;
            for (int c = q; c < 14; c += 4) {
                uint4 r0 = *(const uint4*)(vr + 8 * c);
                uint4 r1 = *(const uint4*)(vr + VSTR + 8 * c);
                *(uint4*)(dst + 8 * c) = lerp8h(r0, r1, f);
            }
        }
        __syncthreads();

        {
            float acc[4] = {0.f, 0.f, 0.f, 0.f};
#pragma unroll
            for (int kt = 0; kt < 7; kt++) {
                uint32 bb0, bb1;
                ldsm_x2t(bb0, bb1,
                         sBb + (kt * 16 + (l & 15)) * (BSTRIDE * 2) + nt * 16);
                uint32 a0, a1, a2, a3;
                ldsm_x4(a0, a1, a2, a3,
                        sAb + (rt * 16 + (l & 15)) * (ASTRIDE * 2)
                            + kt * 32 + (l >> 4) * 16);
                mma16816(acc, a0, a1, a2, a3, bb0, bb1);
            }
            const int rlo = ach0 + rt * 16 + (l >> 2);
            const int rhi = rlo + 8;
            const int col = nt * 8 + 2 * (l & 3);
            const float plo = s_p[rlo];
            const float phi = s_p[rhi];
            float* blo = g_aopart + slot * ZNC + (z * NPT + rlo) * CH + col;
            float* bhi = g_aopart + slot * ZNC + (z * NPT + rhi) * CH + col;
            atomicAdd(blo + 0, acc[0] * plo);
            atomicAdd(blo + 1, acc[1] * plo);
            atomicAdd(bhi + 0, acc[2] * phi);
            atomicAdd(bhi + 1, acc[3] * phi);
        }
        __syncthreads();
    }
}

// ---------------- Kernel C: conv with fused CfF projection ----------------
__global__ __launch_bounds__(256, 4) void conv_kernel(const float* __restrict__ xyz,
                                                      const float* __restrict__ Cf) {
    __shared__ __align__(16) __half s_A[64 * ASTRIDE];
    __shared__ __align__(16) __half s_B[KPAD * BSTRIDE];
    __shared__ float s_d[256];
    __shared__ float s_ao[CH];

    const int tid = threadIdx.x;
    const int b = blockIdx.x;
    const int z = blockIdx.y;
    const int slot = b >> 5;

    // ao = attnout[z,b] = sum of aopart slots
    if (tid < CH) {
        const int off = (z * NPT + b) * CH + tid;
        float acc = 0.f;
#pragma unroll
        for (int s = 0; s < NSLOT; s++) acc += g_aopart[s * ZNC + off];
        s_ao[tid] = acc;
    }
    {
        float bx = xyz[(z * NPT + b) * 3 + 0];
        float by = xyz[(z * NPT + b) * 3 + 1];
        float bz = xyz[(z * NPT + b) * 3 + 2];
        float dx = bx - xyz[(z * NPT + tid) * 3 + 0];
        float dy = by - xyz[(z * NPT + tid) * 3 + 1];
        float dz = bz - xyz[(z * NPT + tid) * 3 + 2];
        s_d[tid] = sqrtf(dx * dx + dy * dy + dz * dz + 1e-12f);
    }
    __syncthreads();

    // B[k][i] = fp16( sum_j Cf[k][i*CH+j] * ao[j] )   (== old CfF quantization)
    {
        for (int e = tid; e < KPAD * CH; e += 256) {
            int k = e >> 4, i = e & 15;
            float acc = 0.f;
            if (k < HD) {
                const float* cp = Cf + k * (CH * CH) + i * CH;
                float4 c0 = *(const float4*)(cp);
                float4 c1 = *(const float4*)(cp + 4);
                float4 c2 = *(const float4*)(cp + 8);
                float4 c3 = *(const float4*)(cp + 12);
                acc = c0.x*s_ao[0]+c0.y*s_ao[1]+c0.z*s_ao[2]+c0.w*s_ao[3]
                    + c1.x*s_ao[4]+c1.y*s_ao[5]+c1.z*s_ao[6]+c1.w*s_ao[7]
                    + c2.x*s_ao[8]+c2.y*s_ao[9]+c2.z*s_ao[10]+c2.w*s_ao[11]
                    + c3.x*s_ao[12]+c3.y*s_ao[13]+c3.z*s_ao[14]+c3.w*s_ao[15];
            }
            s_B[k * BSTRIDE + i] = __float2half(acc);
        }
    }
    __syncthreads();

    const int w = tid >> 5, l = tid & 31;
    const int rt = w >> 1, nt = w & 1;
    uint32 sAb = (uint32)__cvta_generic_to_shared(s_A);
    uint32 sBb = (uint32)__cvta_generic_to_shared(s_B);

    for (int ch = 0; ch < 4; ch++) {
        const int ach0 = ch * 64;
        {
            const int p = tid >> 2, q = tid & 3;
            const float TSCALE = (float)(NTAB - 1) / DMAX;
            float x = s_d[ach0 + p] * TSCALE;
            int i0 = (int)x;
            if (i0 > NTAB - 2) i0 = NTAB - 2;
            float f = x - (float)i0;
            const __half* cr = g_Ctab + (size_t)i0 * VSTR;
            __half* dst = s_A + p * ASTRIDE;
            for (int c = q; c < 14; c += 4) {
                uint4 r0 = *(const uint4*)(cr + 8 * c);
                uint4 r1 = *(const uint4*)(cr + VSTR + 8 * c);
                *(uint4*)(dst + 8 * c) = lerp8h(r0, r1, f);
            }
        }
        __syncthreads();

        {
            float acc[4] = {0.f, 0.f, 0.f, 0.f};
#pragma unroll
            for (int kt = 0; kt < 7; kt++) {
                uint32 bb0, bb1;
                ldsm_x2t(bb0, bb1,
                         sBb + (kt * 16 + (l & 15)) * (BSTRIDE * 2) + nt * 16);
                uint32 a0, a1, a2, a3;
                ldsm_x4(a0, a1, a2, a3,
                        sAb + (rt * 16 + (l & 15)) * (ASTRIDE * 2)
                            + kt * 32 + (l >> 4) * 16);
                mma16816(acc, a0, a1, a2, a3, bb0, bb1);
            }
            const int rlo = ach0 + rt * 16 + (l >> 2);
            const int rhi = rlo + 8;
            const int col = nt * 8 + 2 * (l & 3);
            float* blo = g_outpart + slot * ZNC + (z * NPT + rlo) * CH + col;
            float* bhi = g_outpart + slot * ZNC + (z * NPT + rhi) * CH + col;
            atomicAdd(blo + 0, acc[0]);
            atomicAdd(blo + 1, acc[1]);
            atomicAdd(bhi + 0, acc[2]);
            atomicAdd(bhi + 1, acc[3]);
        }
        __syncthreads();
    }
}

// ---------------- Kernel F: finalize out ----------------
__global__ __launch_bounds__(256) void final_kernel(float* __restrict__ out) {
    const int e = blockIdx.x * 256 + threadIdx.x;
    if (e < ZNC) {
        float acc = 0.f;
#pragma unroll
        for (int s = 0; s < NSLOT; s++) acc += g_outpart[s * ZNC + e];
        out[e] = acc;
    }
}

// ---------------- launch ----------------
extern "C" void kernel_launch(void* const* d_in, const int* in_sizes, int n_in,
                              void* d_out, int out_size) {
    const float* features = (const float*)d_in[0];
    const float* xyz = (const float*)d_in[1];
    const float* Wq = (const float*)d_in[2];
    const float* K0 = (const float*)d_in[3];
    const float* K1 = (const float*)d_in[4];
    const float* Kf = (const float*)d_in[5];
    const float* V0 = (const float*)d_in[6];
    const float* Vf = (const float*)d_in[7];
    const float* C0 = (const float*)d_in[8];
    const float* C1 = (const float*)d_in[9];
    const float* Cf = (const float*)d_in[10];
    float* out = (float*)d_out;

    cudaFuncSetAttribute(build_kernel, cudaFuncAttributeMaxDynamicSharedMemorySize,
                         B_SMEM_FLOATS * (int)sizeof(float));

    build_kernel<<<416, 256, B_SMEM_FLOATS * sizeof(float)>>>(
        features, Wq, Kf, Vf, K0, K1, C0, C1, V0);
    pair_kernel<<<dim3(NPT, Z * HEADS), 256>>>(xyz);
    softmax_p_kernel<<<Z * NPT, 256>>>();
    val_kernel<<<dim3(NPT, Z * HEADS), 256>>>(xyz);
    conv_kernel<<<dim3(NPT, Z), 256>>>(xyz, Cf);
    final_kernel<<<(ZNC + 255) / 256, 256>>>(out);
}

// round 16
// speedup vs baseline: 1.0669x; 1.0669x over previous
#include <cuda_runtime.h>
#include <cuda_fp16.h>
#include <math.h>

#define Z 2
#define NPT 256
#define CH 16
#define HEADS 2
#define NB 10
#define HD 100
#define NBV 3
#define K1STR 102
#define NTAB 1024
#define DMAX 8.7f
#define STEP10 (5.0f / 9.0f)
#define INV10 (9.0f / 5.0f)
#define NSLOT 8
#define ZNC (Z * NPT * CH)
#define ASTRIDE 120
#define BSTRIDE 24
#define KPAD 112
#define VSTR 112

typedef unsigned long long u64t;
typedef unsigned int uint32;

// ---------------- scratch ----------------
__device__ float g_q[HEADS * Z * NPT * CH];
__device__ float g_WfF[HEADS * Z * NPT * HD * CH];   // fp32 (score path) [h][z][b][i][m]
__device__ __half g_VfF[HEADS * Z * NPT * HD * CH];  // fp16 (value path)
__device__ __half g_CfF[Z * NPT * HD * CH];          // fp16 (conv path)
__device__ float g_scores[HEADS * Z * NPT * NPT];    // [h][z][a][b]
__device__ float g_p[HEADS * Z * NPT * NPT];         // [h][z][b][a]
__device__ float g_aopart[NSLOT * ZNC];
__device__ float g_outpart[NSLOT * ZNC];
__device__ float  g_Ktab[HEADS * NTAB * HD];         // fp32 (score path)
__device__ __align__(16) __half g_Ctab[NTAB * VSTR];
__device__ __align__(16) __half g_Vtab[HEADS * NTAB * VSTR];

__device__ __forceinline__ float swishf(float x) {
    return x / (1.0f + __expf(-x));
}
__device__ __forceinline__ void fma2(u64t& d, u64t a, u64t b) {
    asm("fma.rn.f32x2 %0, %1, %2, %0;" : "+l"(d) : "l"(a), "l"(b));
}
__device__ __forceinline__ float up2sum(u64t v) {
    float2 f;
    asm("mov.b64 {%0, %1}, %2;" : "=f"(f.x), "=f"(f.y) : "l"(v));
    return f.x + f.y;
}
__device__ __forceinline__ u64t lds64(const float* p) {
    return *(const u64t*)p;
}
__device__ __forceinline__ void ldsm_x4(uint32& r0, uint32& r1, uint32& r2, uint32& r3,
                                        uint32 addr) {
    asm volatile("ldmatrix.sync.aligned.m8n8.x4.shared.b16 {%0,%1,%2,%3}, [%4];"
                 : "=r"(r0), "=r"(r1), "=r"(r2), "=r"(r3) : "r"(addr));
}
__device__ __forceinline__ void ldsm_x2t(uint32& r0, uint32& r1, uint32 addr) {
    asm volatile("ldmatrix.sync.aligned.m8n8.x2.trans.shared.b16 {%0,%1}, [%2];"
                 : "=r"(r0), "=r"(r1) : "r"(addr));
}
__device__ __forceinline__ void mma16816(float* d, uint32 a0, uint32 a1, uint32 a2,
                                         uint32 a3, uint32 b0, uint32 b1) {
    asm volatile("mma.sync.aligned.m16n8k16.row.col.f32.f16.f16.f32 "
                 "{%0,%1,%2,%3},{%4,%5,%6,%7},{%8,%9},{%0,%1,%2,%3};"
                 : "+f"(d[0]), "+f"(d[1]), "+f"(d[2]), "+f"(d[3])
                 : "r"(a0), "r"(a1), "r"(a2), "r"(a3), "r"(b0), "r"(b1));
}
// 8-half lerp: (r0, r1, frac) -> packed uint4 of fp16
__device__ __forceinline__ uint4 lerp8h(uint4 r0, uint4 r1, float f) {
    float2 a0 = __half22float2(*(__half2*)&r0.x);
    float2 a1 = __half22float2(*(__half2*)&r0.y);
    float2 a2 = __half22float2(*(__half2*)&r0.z);
    float2 a3 = __half22float2(*(__half2*)&r0.w);
    float2 b0 = __half22float2(*(__half2*)&r1.x);
    float2 b1 = __half22float2(*(__half2*)&r1.y);
    float2 b2 = __half22float2(*(__half2*)&r1.z);
    float2 b3 = __half22float2(*(__half2*)&r1.w);
    float2 o0, o1, o2, o3;
    o0.x = fmaf(f, b0.x - a0.x, a0.x); o0.y = fmaf(f, b0.y - a0.y, a0.y);
    o1.x = fmaf(f, b1.x - a1.x, a1.x); o1.y = fmaf(f, b1.y - a1.y, a1.y);
    o2.x = fmaf(f, b2.x - a2.x, a2.x); o2.y = fmaf(f, b2.y - a2.y, a2.y);
    o3.x = fmaf(f, b3.x - a3.x, a3.x); o3.y = fmaf(f, b3.y - a3.y, a3.y);
    __half2 h0 = __float22half2_rn(o0);
    __half2 h1 = __float22half2_rn(o1);
    __half2 h2 = __float22half2_rn(o2);
    __half2 h3 = __float22half2_rn(o3);
    uint4 st;
    st.x = *(uint32*)&h0; st.y = *(uint32*)&h1;
    st.z = *(uint32*)&h2; st.w = *(uint32*)&h3;
    return st;
}

// ---------------- Kernel B: all prep fused (tables + Vtab + proj) ----------------
#define B_SMEM_FLOATS 18240
__global__ __launch_bounds__(256) void build_kernel(const float* __restrict__ features,
                                                    const float* __restrict__ Wq,
                                                    const float* __restrict__ Kf,
                                                    const float* __restrict__ Vf,
                                                    const float* __restrict__ K0,
                                                    const float* __restrict__ K1,
                                                    const float* __restrict__ C0,
                                                    const float* __restrict__ C1,
                                                    const float* __restrict__ V0) {
    extern __shared__ float sm[];
    const int bx = blockIdx.x;
    const int tid = threadIdx.x;

    if (bx < 48) {
        float* s_k0T = sm;            // 1000
        float* s_k1T = sm + 1000;     // 10200
        float* s_bas = sm + 11200;    // 640
        float* s_h1  = sm + 11840;    // 6400
        const int net = bx / 16;
        const int p0 = (bx % 16) * 64;
        const float* K0src = (net < 2) ? (K0 + net * NB * HD) : C0;
        const float* K1src = (net < 2) ? (K1 + net * HD * HD) : C1;

        for (int e = tid; e < NB * HD; e += 256) {
            int n = e / HD, m = e - n * HD;
            s_k0T[m * NB + n] = K0src[e];
        }
        for (int e = tid; e < HD * HD; e += 256) {
            int n = e / HD, m = e - n * HD;
            s_k1T[m * K1STR + n] = K1src[e];
        }
        const float DELTA = DMAX / (float)(NTAB - 1);
        for (int e = tid; e < 64 * NB; e += 256) {
            int p = e / NB, n = e - p * NB;
            float d = (float)(p0 + p) * DELTA;
            float diff = (d - n * STEP10) * INV10;
            s_bas[e] = (fabsf(diff) < 1.0f) ? cospif(0.5f * diff) : 0.0f;
        }
        __syncthreads();

        {
            const int p = tid >> 2, q4 = tid & 3;
            const float* bp = s_bas + p * NB;
            u64t bb0 = lds64(bp), bb1 = lds64(bp + 2), bb2 = lds64(bp + 4),
                 bb3 = lds64(bp + 6), bb4 = lds64(bp + 8);
#pragma unroll 5
            for (int mm = 0; mm < 25; mm++) {
                int m = q4 * 25 + mm;
                const float* kp = s_k0T + m * NB;
                u64t acc = 0ull;
                fma2(acc, bb0, lds64(kp));
                fma2(acc, bb1, lds64(kp + 2));
                fma2(acc, bb2, lds64(kp + 4));
                fma2(acc, bb3, lds64(kp + 6));
                fma2(acc, bb4, lds64(kp + 8));
                s_h1[p * HD + m] = swishf(up2sum(acc));
            }
        }
        __syncthreads();

        {
            const int ty = tid >> 4, tx = tid & 15;
            const float* hbase = s_h1 + ty * 4 * HD;
            const bool tail = tx < 4;
            u64t acc[4][7];
#pragma unroll
            for (int r = 0; r < 4; r++)
#pragma unroll
                for (int j = 0; j < 7; j++) acc[r][j] = 0ull;
#pragma unroll 2
            for (int t = 0; t < 50; t++) {
                u64t h0 = lds64(hbase + 2 * t);
                u64t h1v = lds64(hbase + HD + 2 * t);
                u64t h2v = lds64(hbase + 2 * HD + 2 * t);
                u64t h3v = lds64(hbase + 3 * HD + 2 * t);
#pragma unroll
                for (int j = 0; j < 6; j++) {
                    u64t kv = lds64(s_k1T + (tx + 16 * j) * K1STR + 2 * t);
                    fma2(acc[0][j], h0, kv);
                    fma2(acc[1][j], h1v, kv);
                    fma2(acc[2][j], h2v, kv);
                    fma2(acc[3][j], h3v, kv);
                }
                if (tail) {
                    u64t kv = lds64(s_k1T + (tx + 96) * K1STR + 2 * t);
                    fma2(acc[0][6], h0, kv);
                    fma2(acc[1][6], h1v, kv);
                    fma2(acc[2][6], h2v, kv);
                    fma2(acc[3][6], h3v, kv);
                }
            }
            if (net < 2) {
                float* tabf = g_Ktab + (size_t)net * NTAB * HD;
#pragma unroll
                for (int r = 0; r < 4; r++) {
                    float* row = tabf + (size_t)(p0 + ty * 4 + r) * HD;
#pragma unroll
                    for (int j = 0; j < 6; j++)
                        row[tx + 16 * j] = swishf(up2sum(acc[r][j]));
                    if (tail)
                        row[tx + 96] = swishf(up2sum(acc[r][6]));
                }
            } else {
#pragma unroll
                for (int r = 0; r < 4; r++) {
                    __half* row = g_Ctab + (size_t)(p0 + ty * 4 + r) * VSTR;
#pragma unroll
                    for (int j = 0; j < 6; j++)
                        row[tx + 16 * j] = __float2half(swishf(up2sum(acc[r][j])));
                    if (tail)
                        row[tx + 96] = __float2half(swishf(up2sum(acc[r][6])));
                    else
                        row[96 + tx] = __half(0);
                }
            }
        }
    } else if (bx < 80) {
        const int t = bx - 48;
        const int h = t >> 4;
        const int p0 = (t & 15) * 64;
        const int p = tid >> 2, q = tid & 3;
        const float DELTA = DMAX / (float)(NTAB - 1);
        float d = (float)(p0 + p) * DELTA;
        float bas[NBV];
#pragma unroll
        for (int n = 0; n < NBV; n++) {
            float diff = (d - n * 2.5f) * 0.4f;
            bas[n] = (fabsf(diff) < 1.0f) ? cospif(0.5f * diff) : 0.0f;
        }
        const float* v = V0 + h * NBV * HD;
        __half* row = g_Vtab + (size_t)h * NTAB * VSTR + (size_t)(p0 + p) * VSTR;
#pragma unroll 5
        for (int u = 0; u < 25; u++) {
            int m = q * 25 + u;
            float acc = bas[0] * v[m] + bas[1] * v[HD + m] + bas[2] * v[2 * HD + m];
            row[m] = __float2half(swishf(acc));
        }
        if (q == 3) {
            *(uint2*)(row + 100) = make_uint2(0u, 0u);
            *(uint2*)(row + 104) = make_uint2(0u, 0u);
            *(uint2*)(row + 108) = make_uint2(0u, 0u);
        }
    } else {
        // proj
        float* fs = sm;
        const int t = bx - 80;
        const int zb = t >> 2;
        const int z = zb >> 5;
        const int b0 = (zb & 31) * 8;
        const int sl = t & 3;
        if (tid < 8 * CH) fs[tid] = features[(z * NPT + b0) * CH + tid];
        __syncthreads();

        if (sl == 0) {
            const int bl = tid >> 5, r = tid & 31, h = r >> 4, o = r & 15;
            float acc = 0.f;
#pragma unroll
            for (int i = 0; i < CH; i++) acc += fs[bl * CH + i] * Wq[(h * CH + o) * CH + i];
            g_q[((h * Z + z) * NPT + b0 + bl) * CH + o] = acc;
        }

        for (int e = tid; e < HEADS * 25 * CH; e += 256) {
            const int h = e / 400;
            const int rr = e - h * 400;
            const int i = rr / 25, mm = rr - i * 25;
            const int m = sl * 25 + mm;
            const int r = i * HD + m;
            const float* kfp = Kf + (h * HD + m) * (CH * CH) + i * CH;
            const float* vfp = Vf + (h * HD + m) * (CH * CH) + i * CH;
            float4 k0 = *(const float4*)(kfp);
            float4 k1 = *(const float4*)(kfp + 4);
            float4 k2 = *(const float4*)(kfp + 8);
            float4 k3 = *(const float4*)(kfp + 12);
            float4 v0 = *(const float4*)(vfp);
            float4 v1 = *(const float4*)(vfp + 4);
            float4 v2 = *(const float4*)(vfp + 8);
            float4 v3 = *(const float4*)(vfp + 12);
#pragma unroll
            for (int bl = 0; bl < 8; bl++) {
                const float* f = fs + bl * CH;
                float aK = k0.x*f[0]+k0.y*f[1]+k0.z*f[2]+k0.w*f[3]
                         + k1.x*f[4]+k1.y*f[5]+k1.z*f[6]+k1.w*f[7]
                         + k2.x*f[8]+k2.y*f[9]+k2.z*f[10]+k2.w*f[11]
                         + k3.x*f[12]+k3.y*f[13]+k3.z*f[14]+k3.w*f[15];
                float aV = v0.x*f[0]+v0.y*f[1]+v0.z*f[2]+v0.w*f[3]
                         + v1.x*f[4]+v1.y*f[5]+v1.z*f[6]+v1.w*f[7]
                         + v2.x*f[8]+v2.y*f[9]+v2.z*f[10]+v2.w*f[11]
                         + v3.x*f[12]+v3.y*f[13]+v3.z*f[14]+v3.w*f[15];
                int o = ((h * Z + z) * NPT + b0 + bl) * (HD * CH) + r;
                g_WfF[o] = aK;
                g_VfF[o] = __float2half(aV);
            }
        }
    }
}

// ---------------- Kernel P: scores via split-fp16 MMA (fp32-accurate) ----------------
__global__ __launch_bounds__(256, 4) void pair_kernel(const float* __restrict__ xyz) {
    __shared__ __align__(16) __half s_Ah[64 * ASTRIDE];
    __shared__ __align__(16) __half s_Al[64 * ASTRIDE];
    __shared__ __align__(16) __half s_Bh[KPAD * BSTRIDE];
    __shared__ __align__(16) __half s_Bl[KPAD * BSTRIDE];
    __shared__ float s_d[256];
    __shared__ float s_red[64];

    const int tid = threadIdx.x;
    const int b = blockIdx.x;
    const int z = blockIdx.y >> 1;
    const int h = blockIdx.y & 1;

    {
        const float* src = g_WfF + ((size_t)((h * Z + z) * NPT + b)) * (HD * CH);
        for (int e = tid; e < KPAD * CH; e += 256) {
            int k = e >> 4, i = e & 15;
            float w = (k < HD) ? src[i * HD + k] : 0.0f;
            __half hh = __float2half_rn(w);
            s_Bh[k * BSTRIDE + i] = hh;
            s_Bl[k * BSTRIDE + i] = __float2half_rn(w - __half2float(hh));
        }
    }
    {
        float bx = xyz[(z * NPT + b) * 3 + 0];
        float by = xyz[(z * NPT + b) * 3 + 1];
        float bz = xyz[(z * NPT + b) * 3 + 2];
        float dx = bx - xyz[(z * NPT + tid) * 3 + 0];
        float dy = by - xyz[(z * NPT + tid) * 3 + 1];
        float dz = bz - xyz[(z * NPT + tid) * 3 + 2];
        s_d[tid] = sqrtf(dx * dx + dy * dy + dz * dz + 1e-12f);
    }
    if (tid < 192) {
        int row = tid / 3, off = 100 + 4 * (tid % 3);
        *(uint2*)(s_Ah + row * ASTRIDE + off) = make_uint2(0u, 0u);
        *(uint2*)(s_Al + row * ASTRIDE + off) = make_uint2(0u, 0u);
    }
    __syncthreads();

    const int w = tid >> 5, l = tid & 31;
    const int rt = w >> 1, nt = w & 1;
    uint32 sAh = (uint32)__cvta_generic_to_shared(s_Ah);
    uint32 sAl = (uint32)__cvta_generic_to_shared(s_Al);
    uint32 sBh = (uint32)__cvta_generic_to_shared(s_Bh);
    uint32 sBl = (uint32)__cvta_generic_to_shared(s_Bl);

    for (int ch = 0; ch < 4; ch++) {
        const int ach0 = ch * 64;
        {
            const int p = tid >> 2, q = tid & 3;
            const float TSCALE = (float)(NTAB - 1) / DMAX;
            float x = s_d[ach0 + p] * TSCALE;
            int i0 = (int)x;
            if (i0 > NTAB - 2) i0 = NTAB - 2;
            float f = x - (float)i0;
            const float* kr = g_Ktab + ((size_t)h * NTAB + i0) * HD;
            __half* dh = s_Ah + p * ASTRIDE;
            __half* dl = s_Al + p * ASTRIDE;
            for (int c = q; c < 25; c += 4) {
                float4 a0v = *(const float4*)(kr + 4 * c);
                float4 a1v = *(const float4*)(kr + HD + 4 * c);
                float4 o;
                o.x = fmaf(f, a1v.x - a0v.x, a0v.x);
                o.y = fmaf(f, a1v.y - a0v.y, a0v.y);
                o.z = fmaf(f, a1v.z - a0v.z, a0v.z);
                o.w = fmaf(f, a1v.w - a0v.w, a0v.w);
                __half2 h01 = __float22half2_rn(make_float2(o.x, o.y));
                __half2 h23 = __float22half2_rn(make_float2(o.z, o.w));
                float2 r01 = __half22float2(h01);
                float2 r23 = __half22float2(h23);
                __half2 l01 = __float22half2_rn(make_float2(o.x - r01.x, o.y - r01.y));
                __half2 l23 = __float22half2_rn(make_float2(o.z - r23.x, o.w - r23.y));
                uint2 sth, stl;
                sth.x = *(uint32*)&h01; sth.y = *(uint32*)&h23;
                stl.x = *(uint32*)&l01; stl.y = *(uint32*)&l23;
                *(uint2*)(dh + 4 * c) = sth;
                *(uint2*)(dl + 4 * c) = stl;
            }
        }
        __syncthreads();

        {
            float acc[4] = {0.f, 0.f, 0.f, 0.f};
#pragma unroll
            for (int kt = 0; kt < 7; kt++) {
                uint32 boff = (kt * 16 + (l & 15)) * (BSTRIDE * 2) + nt * 16;
                uint32 bh0, bh1, bl0, bl1;
                ldsm_x2t(bh0, bh1, sBh + boff);
                ldsm_x2t(bl0, bl1, sBl + boff);
                uint32 aoff = (rt * 16 + (l & 15)) * (ASTRIDE * 2)
                            + kt * 32 + (l >> 4) * 16;
                uint32 a0, a1, a2, a3, c0, c1, c2, c3;
                ldsm_x4(a0, a1, a2, a3, sAh + aoff);
                ldsm_x4(c0, c1, c2, c3, sAl + aoff);
                mma16816(acc, a0, a1, a2, a3, bh0, bh1);
                mma16816(acc, a0, a1, a2, a3, bl0, bl1);
                mma16816(acc, c0, c1, c2, c3, bh0, bh1);
            }
            const int rlo = ach0 + rt * 16 + (l >> 2);
            const int rhi = rlo + 8;
            const int col = nt * 8 + 2 * (l & 3);
            const int qbase = ((h * Z + z) * NPT) * CH;
            float2 qlo = *(const float2*)(g_q + qbase + rlo * CH + col);
            float2 qhi = *(const float2*)(g_q + qbase + rhi * CH + col);
            float slo = acc[0] * qlo.x + acc[1] * qlo.y;
            float shi = acc[2] * qhi.x + acc[3] * qhi.y;
            slo += __shfl_xor_sync(0xffffffffu, slo, 1);
            slo += __shfl_xor_sync(0xffffffffu, slo, 2);
            shi += __shfl_xor_sync(0xffffffffu, shi, 1);
            shi += __shfl_xor_sync(0xffffffffu, shi, 2);
            if (nt == 1 && (l & 3) == 0) {
                s_red[rt * 16 + (l >> 2)] = slo;
                s_red[rt * 16 + 8 + (l >> 2)] = shi;
            }
            __syncthreads();
            if (nt == 0 && (l & 3) == 0) {
                const int rowl = rt * 16 + (l >> 2);
                const int rowh = rowl + 8;
                g_scores[((h * Z + z) * NPT + (ach0 + rowl)) * NPT + b] =
                    (slo + s_red[rowl]) * (1.0f / CH);
                g_scores[((h * Z + z) * NPT + (ach0 + rowh)) * NPT + b] =
                    (shi + s_red[rowh]) * (1.0f / CH);
            }
        }
        __syncthreads();
    }
}

// ---------------- Kernel S: softmax -> transposed p; zero aopart ----------------
__global__ __launch_bounds__(256) void softmax_p_kernel() {
    const int bid = blockIdx.x;
    const int z = bid / NPT, a = bid % NPT;
    const int tid = threadIdx.x;
    const int wid = tid >> 5, lane = tid & 31;
    __shared__ float swr[8];

#pragma unroll
    for (int h = 0; h < HEADS; h++) {
        float sc = g_scores[((h * Z + z) * NPT + a) * NPT + tid];
        float m = sc;
#pragma unroll
        for (int s = 16; s > 0; s >>= 1) m = fmaxf(m, __shfl_xor_sync(0xffffffffu, m, s));
        if (lane == 0) swr[wid] = m;
        __syncthreads();
        float mx = swr[0];
#pragma unroll
        for (int j = 1; j < 8; j++) mx = fmaxf(mx, swr[j]);
        __syncthreads();
        float e = __expf(sc - mx);
        float sum = e;
#pragma unroll
        for (int s = 16; s > 0; s >>= 1) sum += __shfl_xor_sync(0xffffffffu, sum, s);
        if (lane == 0) swr[wid] = sum;
        __syncthreads();
        float tot = swr[0];
#pragma unroll
        for (int j = 1; j < 8; j++) tot += swr[j];
        __syncthreads();
        g_p[((h * Z + z) * NPT + tid) * NPT + a] = e / tot;
    }
    if (tid < 128) g_aopart[bid * 128 + tid] = 0.0f;
}

// ---------------- Kernel V: value contraction, 16B gathers + mma.sync ----------------
__global__ __launch_bounds__(256, 4) void val_kernel(const float* __restrict__ xyz) {
    __shared__ __align__(16) __half s_A[64 * ASTRIDE];
    __shared__ __align__(16) __half s_B[KPAD * BSTRIDE];
    __shared__ float s_d[256];
    __shared__ float s_p[256];

    const int tid = threadIdx.x;
    const int b = blockIdx.x;
    const int z = blockIdx.y >> 1;
    const int h = blockIdx.y & 1;
    const int slot = b >> 5;

    {
        const __half* src = g_VfF + ((size_t)((h * Z + z) * NPT + b)) * (HD * CH);
        for (int e = tid; e < KPAD * CH; e += 256) {
            int k = e >> 4, i = e & 15;
            s_B[k * BSTRIDE + i] = (k < HD) ? src[i * HD + k] : __half(0);
        }
    }
    {
        float bx = xyz[(z * NPT + b) * 3 + 0];
        float by = xyz[(z * NPT + b) * 3 + 1];
        float bz = xyz[(z * NPT + b) * 3 + 2];
        float dx = bx - xyz[(z * NPT + tid) * 3 + 0];
        float dy = by - xyz[(z * NPT + tid) * 3 + 1];
        float dz = bz - xyz[(z * NPT + tid) * 3 + 2];
        s_d[tid] = sqrtf(dx * dx + dy * dy + dz * dz + 1e-12f);
        s_p[tid] = g_p[((h * Z + z) * NPT + b) * NPT + tid];
    }
    __syncthreads();

    const int w = tid >> 5, l = tid & 31;
    const int rt = w >> 1, nt = w & 1;
    uint32 sAb = (uint32)__cvta_generic_to_shared(s_A);
    uint32 sBb = (uint32)__cvta_generic_to_shared(s_B);

    for (int ch = 0; ch < 4; ch++) {
        const int ach0 = ch * 64;
        {
            const int p = tid >> 2, q = tid & 3;
            const float TSCALE = (float)(NTAB - 1) / DMAX;
            float x = s_d[ach0 + p] * TSCALE;
            int i0 = (int)x;
            if (i0 > NTAB - 2) i0 = NTAB - 2;
            float f = x - (float)i0;
            const __half* vr = g_Vtab + ((size_t)h * NTAB + i0) * VSTR;
            __half* dst = s_A + p * ASTRIDE;
            for (int c = q; c < 14; c += 4) {
                uint4 r0 = *(const uint4*)(vr + 8 * c);
                uint4 r1 = *(const uint4*)(vr + VSTR + 8 * c);
                *(uint4*)(dst + 8 * c) = lerp8h(r0, r1, f);
            }
        }
        __syncthreads();

        {
            float acc[4] = {0.f, 0.f, 0.f, 0.f};
#pragma unroll
            for (int kt = 0; kt < 7; kt++) {
                uint32 bb0, bb1;
                ldsm_x2t(bb0, bb1,
                         sBb + (kt * 16 + (l & 15)) * (BSTRIDE * 2) + nt * 16);
                uint32 a0, a1, a2, a3;
                ldsm_x4(a0, a1, a2, a3,
                        sAb + (rt * 16 + (l & 15)) * (ASTRIDE * 2)
                            + kt * 32 + (l >> 4) * 16);
                mma16816(acc, a0, a1, a2, a3, bb0, bb1);
            }
            const int rlo = ach0 + rt * 16 + (l >> 2);
            const int rhi = rlo + 8;
            const int col = nt * 8 + 2 * (l & 3);
            const float plo = s_p[rlo];
            const float phi = s_p[rhi];
            float* blo = g_aopart + slot * ZNC + (z * NPT + rlo) * CH + col;
            float* bhi = g_aopart + slot * ZNC + (z * NPT + rhi) * CH + col;
            atomicAdd(blo + 0, acc[0] * plo);
            atomicAdd(blo + 1, acc[1] * plo);
            atomicAdd(bhi + 0, acc[2] * phi);
            atomicAdd(bhi + 1, acc[3] * phi);
        }
        __syncthreads();
    }
}

// ---------------- Kernel C1: sum aopart + CfF projection (fp16 out); zero outpart ----------------
__global__ __launch_bounds__(256) void cff_kernel(const float* __restrict__ Cf) {
    const int bx = blockIdx.x;
    const int z = bx >> 7;
    const int b0 = ((bx >> 2) & 31) * 8;
    const int sl = bx & 3;
    const int tid = threadIdx.x;
    __shared__ float ao[8 * CH];
    if (tid < 8 * CH) {
        const int off = (z * NPT + b0) * CH + tid;
        float acc = 0.f;
#pragma unroll
        for (int s = 0; s < NSLOT; s++) acc += g_aopart[s * ZNC + off];
        ao[tid] = acc;
    }
    g_outpart[bx * 256 + tid] = 0.0f;
    __syncthreads();
    for (int e = tid; e < 25 * CH; e += 256) {
        const int i = e / 25, mm = e - i * 25;
        const int m = sl * 25 + mm;
        const int r = i * HD + m;
        const float* cp = Cf + m * (CH * CH) + i * CH;
        float4 c0 = *(const float4*)(cp);
        float4 c1 = *(const float4*)(cp + 4);
        float4 c2 = *(const float4*)(cp + 8);
        float4 c3 = *(const float4*)(cp + 12);
#pragma unroll
        for (int bl = 0; bl < 8; bl++) {
            const float* f = ao + bl * CH;
            float acc = c0.x*f[0]+c0.y*f[1]+c0.z*f[2]+c0.w*f[3]
                      + c1.x*f[4]+c1.y*f[5]+c1.z*f[6]+c1.w*f[7]
                      + c2.x*f[8]+c2.y*f[9]+c2.z*f[10]+c2.w*f[11]
                      + c3.x*f[12]+c3.y*f[13]+c3.z*f[14]+c3.w*f[15];
            g_CfF[(z * NPT + b0 + bl) * (HD * CH) + r] = __float2half(acc);
        }
    }
}

// ---------------- Kernel C2: final conv, 16B gathers + mma.sync ----------------
__global__ __launch_bounds__(256, 4) void conv_kernel(const float* __restrict__ xyz) {
    __shared__ __align__(16) __half s_A[64 * ASTRIDE];
    __shared__ __align__(16) __half s_B[KPAD * BSTRIDE];
    __shared__ float s_d[256];

    const int tid = threadIdx.x;
    const int b = blockIdx.x;
    const int z = blockIdx.y;
    const int slot = b >> 5;

    {
        const __half* src = g_CfF + ((size_t)(z * NPT + b)) * (HD * CH);
        for (int e = tid; e < KPAD * CH; e += 256) {
            int k = e >> 4, i = e & 15;
            s_B[k * BSTRIDE + i] = (k < HD) ? src[i * HD + k] : __half(0);
        }
    }
    {
        float bx = xyz[(z * NPT + b) * 3 + 0];
        float by = xyz[(z * NPT + b) * 3 + 1];
        float bz = xyz[(z * NPT + b) * 3 + 2];
        float dx = bx - xyz[(z * NPT + tid) * 3 + 0];
        float dy = by - xyz[(z * NPT + tid) * 3 + 1];
        float dz = bz - xyz[(z * NPT + tid) * 3 + 2];
        s_d[tid] = sqrtf(dx * dx + dy * dy + dz * dz + 1e-12f);
    }
    __syncthreads();

    const int w = tid >> 5, l = tid & 31;
    const int rt = w >> 1, nt = w & 1;
    uint32 sAb = (uint32)__cvta_generic_to_shared(s_A);
    uint32 sBb = (uint32)__cvta_generic_to_shared(s_B);

    for (int ch = 0; ch < 4; ch++) {
        const int ach0 = ch * 64;
        {
            const int p = tid >> 2, q = tid & 3;
            const float TSCALE = (float)(NTAB - 1) / DMAX;
            float x = s_d[ach0 + p] * TSCALE;
            int i0 = (int)x;
            if (i0 > NTAB - 2) i0 = NTAB - 2;
            float f = x - (float)i0;
            const __half* cr = g_Ctab + (size_t)i0 * VSTR;
            __half* dst = s_A + p * ASTRIDE;
            for (int c = q; c < 14; c += 4) {
                uint4 r0 = *(const uint4*)(cr + 8 * c);
                uint4 r1 = *(const uint4*)(cr + VSTR + 8 * c);
                *(uint4*)(dst + 8 * c) = lerp8h(r0, r1, f);
            }
        }
        __syncthreads();

        {
            float acc[4] = {0.f, 0.f, 0.f, 0.f};
#pragma unroll
            for (int kt = 0; kt < 7; kt++) {
                uint32 bb0, bb1;
                ldsm_x2t(bb0, bb1,
                         sBb + (kt * 16 + (l & 15)) * (BSTRIDE * 2) + nt * 16);
                uint32 a0, a1, a2, a3;
                ldsm_x4(a0, a1, a2, a3,
                        sAb + (rt * 16 + (l & 15)) * (ASTRIDE * 2)
                            + kt * 32 + (l >> 4) * 16);
                mma16816(acc, a0, a1, a2, a3, bb0, bb1);
            }
            const int rlo = ach0 + rt * 16 + (l >> 2);
            const int rhi = rlo + 8;
            const int col = nt * 8 + 2 * (l & 3);
            float* blo = g_outpart + slot * ZNC + (z * NPT + rlo) * CH + col;
            float* bhi = g_outpart + slot * ZNC + (z * NPT + rhi) * CH + col;
            atomicAdd(blo + 0, acc[0]);
            atomicAdd(blo + 1, acc[1]);
            atomicAdd(bhi + 0, acc[2]);
            atomicAdd(bhi + 1, acc[3]);
        }
        __syncthreads();
    }
}

// ---------------- Kernel F: finalize out ----------------
__global__ __launch_bounds__(256) void final_kernel(float* __restrict__ out) {
    const int e = blockIdx.x * 256 + threadIdx.x;
    if (e < ZNC) {
        float acc = 0.f;
#pragma unroll
        for (int s = 0; s < NSLOT; s++) acc += g_outpart[s * ZNC + e];
        out[e] = acc;
    }
}

// ---------------- launch ----------------
extern "C" void kernel_launch(void* const* d_in, const int* in_sizes, int n_in,
                              void* d_out, int out_size) {
    const float* features = (const float*)d_in[0];
    const float* xyz = (const float*)d_in[1];
    const float* Wq = (const float*)d_in[2];
    const float* K0 = (const float*)d_in[3];
    const float* K1 = (const float*)d_in[4];
    const float* Kf = (const float*)d_in[5];
    const float* V0 = (const float*)d_in[6];
    const float* Vf = (const float*)d_in[7];
    const float* C0 = (const float*)d_in[8];
    const float* C1 = (const float*)d_in[9];
    const float* Cf = (const float*)d_in[10];
    float* out = (float*)d_out;

    cudaFuncSetAttribute(build_kernel, cudaFuncAttributeMaxDynamicSharedMemorySize,
                         B_SMEM_FLOATS * (int)sizeof(float));

    build_kernel<<<336, 256, B_SMEM_FLOATS * sizeof(float)>>>(
        features, Wq, Kf, Vf, K0, K1, C0, C1, V0);
    pair_kernel<<<dim3(NPT, Z * HEADS), 256>>>(xyz);
    softmax_p_kernel<<<Z * NPT, 256>>>();
    val_kernel<<<dim3(NPT, Z * HEADS), 256>>>(xyz);
    cff_kernel<<<256, 256>>>(Cf);
    conv_kernel<<<dim3(NPT, Z), 256>>>(xyz);
    final_kernel<<<(ZNC + 255) / 256, 256>>>(out);
}

// round 17
// speedup vs baseline: 1.0784x; 1.0108x over previous
#include <cuda_runtime.h>
#include <cuda_fp16.h>
#include <math.h>

#define Z 2
#define NPT 256
#define CH 16
#define HEADS 2
#define NB 10
#define HD 100
#define NBV 3
#define K1STR 102
#define NTAB 512
#define DMAX 8.7f
#define STEP10 (5.0f / 9.0f)
#define INV10 (9.0f / 5.0f)
#define NSLOT 8
#define ZNC (Z * NPT * CH)
#define ASTRIDE 120
#define BSTRIDE 24
#define KPAD 112
#define VSTR 112

typedef unsigned long long u64t;
typedef unsigned int uint32;

// ---------------- scratch ----------------
__device__ float g_q[HEADS * Z * NPT * CH];
__device__ __half g_WfFh[HEADS * Z * NPT * HD * CH]; // fp16 hi (score path) [h][z][b][i][m]
__device__ __half g_WfFl[HEADS * Z * NPT * HD * CH]; // fp16 lo residual
__device__ __half g_VfF[HEADS * Z * NPT * HD * CH];  // fp16 (value path)
__device__ __half g_CfF[Z * NPT * HD * CH];          // fp16 (conv path)
__device__ float g_scores[HEADS * Z * NPT * NPT];    // [h][z][a][b]
__device__ float g_p[HEADS * Z * NPT * NPT];         // [h][z][b][a]
__device__ float g_aopart[NSLOT * ZNC];
__device__ float g_outpart[NSLOT * ZNC];
__device__ float  g_Ktab[HEADS * NTAB * HD];         // fp32 (score path)
__device__ __align__(16) __half g_Ctab[NTAB * VSTR];
__device__ __align__(16) __half g_Vtab[HEADS * NTAB * VSTR];

__device__ __forceinline__ float swishf(float x) {
    return x / (1.0f + __expf(-x));
}
__device__ __forceinline__ void fma2(u64t& d, u64t a, u64t b) {
    asm("fma.rn.f32x2 %0, %1, %2, %0;" : "+l"(d) : "l"(a), "l"(b));
}
__device__ __forceinline__ float up2sum(u64t v) {
    float2 f;
    asm("mov.b64 {%0, %1}, %2;" : "=f"(f.x), "=f"(f.y) : "l"(v));
    return f.x + f.y;
}
__device__ __forceinline__ u64t lds64(const float* p) {
    return *(const u64t*)p;
}
__device__ __forceinline__ void ldsm_x4(uint32& r0, uint32& r1, uint32& r2, uint32& r3,
                                        uint32 addr) {
    asm volatile("ldmatrix.sync.aligned.m8n8.x4.shared.b16 {%0,%1,%2,%3}, [%4];"
                 : "=r"(r0), "=r"(r1), "=r"(r2), "=r"(r3) : "r"(addr));
}
__device__ __forceinline__ void ldsm_x2t(uint32& r0, uint32& r1, uint32 addr) {
    asm volatile("ldmatrix.sync.aligned.m8n8.x2.trans.shared.b16 {%0,%1}, [%2];"
                 : "=r"(r0), "=r"(r1) : "r"(addr));
}
__device__ __forceinline__ void mma16816(float* d, uint32 a0, uint32 a1, uint32 a2,
                                         uint32 a3, uint32 b0, uint32 b1) {
    asm volatile("mma.sync.aligned.m16n8k16.row.col.f32.f16.f16.f32 "
                 "{%0,%1,%2,%3},{%4,%5,%6,%7},{%8,%9},{%0,%1,%2,%3};"
                 : "+f"(d[0]), "+f"(d[1]), "+f"(d[2]), "+f"(d[3])
                 : "r"(a0), "r"(a1), "r"(a2), "r"(a3), "r"(b0), "r"(b1));
}
// 8-half lerp: (r0, r1, frac) -> packed uint4 of fp16
__device__ __forceinline__ uint4 lerp8h(uint4 r0, uint4 r1, float f) {
    float2 a0 = __half22float2(*(__half2*)&r0.x);
    float2 a1 = __half22float2(*(__half2*)&r0.y);
    float2 a2 = __half22float2(*(__half2*)&r0.z);
    float2 a3 = __half22float2(*(__half2*)&r0.w);
    float2 b0 = __half22float2(*(__half2*)&r1.x);
    float2 b1 = __half22float2(*(__half2*)&r1.y);
    float2 b2 = __half22float2(*(__half2*)&r1.z);
    float2 b3 = __half22float2(*(__half2*)&r1.w);
    float2 o0, o1, o2, o3;
    o0.x = fmaf(f, b0.x - a0.x, a0.x); o0.y = fmaf(f, b0.y - a0.y, a0.y);
    o1.x = fmaf(f, b1.x - a1.x, a1.x); o1.y = fmaf(f, b1.y - a1.y, a1.y);
    o2.x = fmaf(f, b2.x - a2.x, a2.x); o2.y = fmaf(f, b2.y - a2.y, a2.y);
    o3.x = fmaf(f, b3.x - a3.x, a3.x); o3.y = fmaf(f, b3.y - a3.y, a3.y);
    __half2 h0 = __float22half2_rn(o0);
    __half2 h1 = __float22half2_rn(o1);
    __half2 h2 = __float22half2_rn(o2);
    __half2 h3 = __float22half2_rn(o3);
    uint4 st;
    st.x = *(uint32*)&h0; st.y = *(uint32*)&h1;
    st.z = *(uint32*)&h2; st.w = *(uint32*)&h3;
    return st;
}

// ---------------- Kernel B: all prep fused (tables + Vtab + proj) ----------------
#define B_SMEM_FLOATS 18240
__global__ __launch_bounds__(256) void build_kernel(const float* __restrict__ features,
                                                    const float* __restrict__ Wq,
                                                    const float* __restrict__ Kf,
                                                    const float* __restrict__ Vf,
                                                    const float* __restrict__ K0,
                                                    const float* __restrict__ K1,
                                                    const float* __restrict__ C0,
                                                    const float* __restrict__ C1,
                                                    const float* __restrict__ V0) {
    extern __shared__ float sm[];
    const int bx = blockIdx.x;
    const int tid = threadIdx.x;

    if (bx < 24) {
        float* s_k0T = sm;            // 1000
        float* s_k1T = sm + 1000;     // 10200
        float* s_bas = sm + 11200;    // 640
        float* s_h1  = sm + 11840;    // 6400
        const int net = bx / 8;
        const int p0 = (bx % 8) * 64;
        const float* K0src = (net < 2) ? (K0 + net * NB * HD) : C0;
        const float* K1src = (net < 2) ? (K1 + net * HD * HD) : C1;

        for (int e = tid; e < NB * HD; e += 256) {
            int n = e / HD, m = e - n * HD;
            s_k0T[m * NB + n] = K0src[e];
        }
        for (int e = tid; e < HD * HD; e += 256) {
            int n = e / HD, m = e - n * HD;
            s_k1T[m * K1STR + n] = K1src[e];
        }
        const float DELTA = DMAX / (float)(NTAB - 1);
        for (int e = tid; e < 64 * NB; e += 256) {
            int p = e / NB, n = e - p * NB;
            float d = (float)(p0 + p) * DELTA;
            float diff = (d - n * STEP10) * INV10;
            s_bas[e] = (fabsf(diff) < 1.0f) ? cospif(0.5f * diff) : 0.0f;
        }
        __syncthreads();

        {
            const int p = tid >> 2, q4 = tid & 3;
            const float* bp = s_bas + p * NB;
            u64t bb0 = lds64(bp), bb1 = lds64(bp + 2), bb2 = lds64(bp + 4),
                 bb3 = lds64(bp + 6), bb4 = lds64(bp + 8);
#pragma unroll 5
            for (int mm = 0; mm < 25; mm++) {
                int m = q4 * 25 + mm;
                const float* kp = s_k0T + m * NB;
                u64t acc = 0ull;
                fma2(acc, bb0, lds64(kp));
                fma2(acc, bb1, lds64(kp + 2));
                fma2(acc, bb2, lds64(kp + 4));
                fma2(acc, bb3, lds64(kp + 6));
                fma2(acc, bb4, lds64(kp + 8));
                s_h1[p * HD + m] = swishf(up2sum(acc));
            }
        }
        __syncthreads();

        {
            const int ty = tid >> 4, tx = tid & 15;
            const float* hbase = s_h1 + ty * 4 * HD;
            const bool tail = tx < 4;
            u64t acc[4][7];
#pragma unroll
            for (int r = 0; r < 4; r++)
#pragma unroll
                for (int j = 0; j < 7; j++) acc[r][j] = 0ull;
#pragma unroll 2
            for (int t = 0; t < 50; t++) {
                u64t h0 = lds64(hbase + 2 * t);
                u64t h1v = lds64(hbase + HD + 2 * t);
                u64t h2v = lds64(hbase + 2 * HD + 2 * t);
                u64t h3v = lds64(hbase + 3 * HD + 2 * t);
#pragma unroll
                for (int j = 0; j < 6; j++) {
                    u64t kv = lds64(s_k1T + (tx + 16 * j) * K1STR + 2 * t);
                    fma2(acc[0][j], h0, kv);
                    fma2(acc[1][j], h1v, kv);
                    fma2(acc[2][j], h2v, kv);
                    fma2(acc[3][j], h3v, kv);
                }
                if (tail) {
                    u64t kv = lds64(s_k1T + (tx + 96) * K1STR + 2 * t);
                    fma2(acc[0][6], h0, kv);
                    fma2(acc[1][6], h1v, kv);
                    fma2(acc[2][6], h2v, kv);
                    fma2(acc[3][6], h3v, kv);
                }
            }
            if (net < 2) {
                float* tabf = g_Ktab + (size_t)net * NTAB * HD;
#pragma unroll
                for (int r = 0; r < 4; r++) {
                    float* row = tabf + (size_t)(p0 + ty * 4 + r) * HD;
#pragma unroll
                    for (int j = 0; j < 6; j++)
                        row[tx + 16 * j] = swishf(up2sum(acc[r][j]));
                    if (tail)
                        row[tx + 96] = swishf(up2sum(acc[r][6]));
                }
            } else {
#pragma unroll
                for (int r = 0; r < 4; r++) {
                    __half* row = g_Ctab + (size_t)(p0 + ty * 4 + r) * VSTR;
#pragma unroll
                    for (int j = 0; j < 6; j++)
                        row[tx + 16 * j] = __float2half(swishf(up2sum(acc[r][j])));
                    if (tail)
                        row[tx + 96] = __float2half(swishf(up2sum(acc[r][6])));
                    else
                        row[96 + tx] = __half(0);
                }
            }
        }
    } else if (bx < 40) {
        const int t = bx - 24;
        const int h = t >> 3;
        const int p0 = (t & 7) * 64;
        const int p = tid >> 2, q = tid & 3;
        const float DELTA = DMAX / (float)(NTAB - 1);
        float d = (float)(p0 + p) * DELTA;
        float bas[NBV];
#pragma unroll
        for (int n = 0; n < NBV; n++) {
            float diff = (d - n * 2.5f) * 0.4f;
            bas[n] = (fabsf(diff) < 1.0f) ? cospif(0.5f * diff) : 0.0f;
        }
        const float* v = V0 + h * NBV * HD;
        __half* row = g_Vtab + (size_t)h * NTAB * VSTR + (size_t)(p0 + p) * VSTR;
#pragma unroll 5
        for (int u = 0; u < 25; u++) {
            int m = q * 25 + u;
            float acc = bas[0] * v[m] + bas[1] * v[HD + m] + bas[2] * v[2 * HD + m];
            row[m] = __float2half(swishf(acc));
        }
        if (q == 3) {
            *(uint2*)(row + 100) = make_uint2(0u, 0u);
            *(uint2*)(row + 104) = make_uint2(0u, 0u);
            *(uint2*)(row + 108) = make_uint2(0u, 0u);
        }
    } else {
        // proj
        float* fs = sm;
        const int t = bx - 40;
        const int zb = t >> 2;
        const int z = zb >> 5;
        const int b0 = (zb & 31) * 8;
        const int sl = t & 3;
        if (tid < 8 * CH) fs[tid] = features[(z * NPT + b0) * CH + tid];
        __syncthreads();

        if (sl == 0) {
            const int bl = tid >> 5, r = tid & 31, h = r >> 4, o = r & 15;
            float acc = 0.f;
#pragma unroll
            for (int i = 0; i < CH; i++) acc += fs[bl * CH + i] * Wq[(h * CH + o) * CH + i];
            g_q[((h * Z + z) * NPT + b0 + bl) * CH + o] = acc;
        }

        for (int e = tid; e < HEADS * 25 * CH; e += 256) {
            const int h = e / 400;
            const int rr = e - h * 400;
            const int i = rr / 25, mm = rr - i * 25;
            const int m = sl * 25 + mm;
            const int r = i * HD + m;
            const float* kfp = Kf + (h * HD + m) * (CH * CH) + i * CH;
            const float* vfp = Vf + (h * HD + m) * (CH * CH) + i * CH;
            float4 k0 = *(const float4*)(kfp);
            float4 k1 = *(const float4*)(kfp + 4);
            float4 k2 = *(const float4*)(kfp + 8);
            float4 k3 = *(const float4*)(kfp + 12);
            float4 v0 = *(const float4*)(vfp);
            float4 v1 = *(const float4*)(vfp + 4);
            float4 v2 = *(const float4*)(vfp + 8);
            float4 v3 = *(const float4*)(vfp + 12);
#pragma unroll
            for (int bl = 0; bl < 8; bl++) {
                const float* f = fs + bl * CH;
                float aK = k0.x*f[0]+k0.y*f[1]+k0.z*f[2]+k0.w*f[3]
                         + k1.x*f[4]+k1.y*f[5]+k1.z*f[6]+k1.w*f[7]
                         + k2.x*f[8]+k2.y*f[9]+k2.z*f[10]+k2.w*f[11]
                         + k3.x*f[12]+k3.y*f[13]+k3.z*f[14]+k3.w*f[15];
                float aV = v0.x*f[0]+v0.y*f[1]+v0.z*f[2]+v0.w*f[3]
                         + v1.x*f[4]+v1.y*f[5]+v1.z*f[6]+v1.w*f[7]
                         + v2.x*f[8]+v2.y*f[9]+v2.z*f[10]+v2.w*f[11]
                         + v3.x*f[12]+v3.y*f[13]+v3.z*f[14]+v3.w*f[15];
                int o = ((h * Z + z) * NPT + b0 + bl) * (HD * CH) + r;
                __half hh = __float2half_rn(aK);
                g_WfFh[o] = hh;
                g_WfFl[o] = __float2half_rn(aK - __half2float(hh));
                g_VfF[o] = __float2half(aV);
            }
        }
    }
}

// ---------------- Kernel P: scores via split-fp16 MMA (fp32-accurate) ----------------
__global__ __launch_bounds__(256, 4) void pair_kernel(const float* __restrict__ xyz) {
    __shared__ __align__(16) __half s_Ah[64 * ASTRIDE];
    __shared__ __align__(16) __half s_Al[64 * ASTRIDE];
    __shared__ __align__(16) __half s_Bh[KPAD * BSTRIDE];
    __shared__ __align__(16) __half s_Bl[KPAD * BSTRIDE];
    __shared__ float s_d[256];
    __shared__ float s_red[64];

    const int tid = threadIdx.x;
    const int b = blockIdx.x;
    const int z = blockIdx.y >> 1;
    const int h = blockIdx.y & 1;

    {
        const size_t base = ((size_t)((h * Z + z) * NPT + b)) * (HD * CH);
        for (int e = tid; e < KPAD * CH; e += 256) {
            int k = e >> 4, i = e & 15;
            __half wh = __half(0), wl = __half(0);
            if (k < HD) {
                wh = g_WfFh[base + i * HD + k];
                wl = g_WfFl[base + i * HD + k];
            }
            s_Bh[k * BSTRIDE + i] = wh;
            s_Bl[k * BSTRIDE + i] = wl;
        }
    }
    {
        float bx = xyz[(z * NPT + b) * 3 + 0];
        float by = xyz[(z * NPT + b) * 3 + 1];
        float bz = xyz[(z * NPT + b) * 3 + 2];
        float dx = bx - xyz[(z * NPT + tid) * 3 + 0];
        float dy = by - xyz[(z * NPT + tid) * 3 + 1];
        float dz = bz - xyz[(z * NPT + tid) * 3 + 2];
        s_d[tid] = sqrtf(dx * dx + dy * dy + dz * dz + 1e-12f);
    }
    if (tid < 192) {
        int row = tid / 3, off = 100 + 4 * (tid % 3);
        *(uint2*)(s_Ah + row * ASTRIDE + off) = make_uint2(0u, 0u);
        *(uint2*)(s_Al + row * ASTRIDE + off) = make_uint2(0u, 0u);
    }
    __syncthreads();

    const int w = tid >> 5, l = tid & 31;
    const int rt = w >> 1, nt = w & 1;
    uint32 sAh = (uint32)__cvta_generic_to_shared(s_Ah);
    uint32 sAl = (uint32)__cvta_generic_to_shared(s_Al);
    uint32 sBh = (uint32)__cvta_generic_to_shared(s_Bh);
    uint32 sBl = (uint32)__cvta_generic_to_shared(s_Bl);

    for (int ch = 0; ch < 4; ch++) {
        const int ach0 = ch * 64;
        {
            const int p = tid >> 2, q = tid & 3;
            const float TSCALE = (float)(NTAB - 1) / DMAX;
            float x = s_d[ach0 + p] * TSCALE;
            int i0 = (int)x;
            if (i0 > NTAB - 2) i0 = NTAB - 2;
            float f = x - (float)i0;
            const float* kr = g_Ktab + ((size_t)h * NTAB + i0) * HD;
            __half* dh = s_Ah + p * ASTRIDE;
            __half* dl = s_Al + p * ASTRIDE;
            for (int c = q; c < 25; c += 4) {
                float4 a0v = *(const float4*)(kr + 4 * c);
                float4 a1v = *(const float4*)(kr + HD + 4 * c);
                float4 o;
                o.x = fmaf(f, a1v.x - a0v.x, a0v.x);
                o.y = fmaf(f, a1v.y - a0v.y, a0v.y);
                o.z = fmaf(f, a1v.z - a0v.z, a0v.z);
                o.w = fmaf(f, a1v.w - a0v.w, a0v.w);
                __half2 h01 = __float22half2_rn(make_float2(o.x, o.y));
                __half2 h23 = __float22half2_rn(make_float2(o.z, o.w));
                float2 r01 = __half22float2(h01);
                float2 r23 = __half22float2(h23);
                __half2 l01 = __float22half2_rn(make_float2(o.x - r01.x, o.y - r01.y));
                __half2 l23 = __float22half2_rn(make_float2(o.z - r23.x, o.w - r23.y));
                uint2 sth, stl;
                sth.x = *(uint32*)&h01; sth.y = *(uint32*)&h23;
                stl.x = *(uint32*)&l01; stl.y = *(uint32*)&l23;
                *(uint2*)(dh + 4 * c) = sth;
                *(uint2*)(dl + 4 * c) = stl;
            }
        }
        __syncthreads();

        {
            float acc[4] = {0.f, 0.f, 0.f, 0.f};
#pragma unroll
            for (int kt = 0; kt < 7; kt++) {
                uint32 boff = (kt * 16 + (l & 15)) * (BSTRIDE * 2) + nt * 16;
                uint32 bh0, bh1, bl0, bl1;
                ldsm_x2t(bh0, bh1, sBh + boff);
                ldsm_x2t(bl0, bl1, sBl + boff);
                uint32 aoff = (rt * 16 + (l & 15)) * (ASTRIDE * 2)
                            + kt * 32 + (l >> 4) * 16;
                uint32 a0, a1, a2, a3, c0, c1, c2, c3;
                ldsm_x4(a0, a1, a2, a3, sAh + aoff);
                ldsm_x4(c0, c1, c2, c3, sAl + aoff);
                mma16816(acc, a0, a1, a2, a3, bh0, bh1);
                mma16816(acc, a0, a1, a2, a3, bl0, bl1);
                mma16816(acc, c0, c1, c2, c3, bh0, bh1);
            }
            const int rlo = ach0 + rt * 16 + (l >> 2);
            const int rhi = rlo + 8;
            const int col = nt * 8 + 2 * (l & 3);
            const int qbase = ((h * Z + z) * NPT) * CH;
            float2 qlo = *(const float2*)(g_q + qbase + rlo * CH + col);
            float2 qhi = *(const float2*)(g_q + qbase + rhi * CH + col);
            float slo = acc[0] * qlo.x + acc[1] * qlo.y;
            float shi = acc[2] * qhi.x + acc[3] * qhi.y;
            slo += __shfl_xor_sync(0xffffffffu, slo, 1);
            slo += __shfl_xor_sync(0xffffffffu, slo, 2);
            shi += __shfl_xor_sync(0xffffffffu, shi, 1);
            shi += __shfl_xor_sync(0xffffffffu, shi, 2);
            if (nt == 1 && (l & 3) == 0) {
                s_red[rt * 16 + (l >> 2)] = slo;
                s_red[rt * 16 + 8 + (l >> 2)] = shi;
            }
            __syncthreads();
            if (nt == 0 && (l & 3) == 0) {
                const int rowl = rt * 16 + (l >> 2);
                const int rowh = rowl + 8;
                g_scores[((h * Z + z) * NPT + (ach0 + rowl)) * NPT + b] =
                    (slo + s_red[rowl]) * (1.0f / CH);
                g_scores[((h * Z + z) * NPT + (ach0 + rowh)) * NPT + b] =
                    (shi + s_red[rowh]) * (1.0f / CH);
            }
        }
        __syncthreads();
    }
}

// ---------------- Kernel S: softmax -> transposed p; zero aopart ----------------
__global__ __launch_bounds__(256) void softmax_p_kernel() {
    const int bid = blockIdx.x;
    const int z = bid / NPT, a = bid % NPT;
    const int tid = threadIdx.x;
    const int wid = tid >> 5, lane = tid & 31;
    __shared__ float swr[8];

#pragma unroll
    for (int h = 0; h < HEADS; h++) {
        float sc = g_scores[((h * Z + z) * NPT + a) * NPT + tid];
        float m = sc;
#pragma unroll
        for (int s = 16; s > 0; s >>= 1) m = fmaxf(m, __shfl_xor_sync(0xffffffffu, m, s));
        if (lane == 0) swr[wid] = m;
        __syncthreads();
        float mx = swr[0];
#pragma unroll
        for (int j = 1; j < 8; j++) mx = fmaxf(mx, swr[j]);
        __syncthreads();
        float e = __expf(sc - mx);
        float sum = e;
#pragma unroll
        for (int s = 16; s > 0; s >>= 1) sum += __shfl_xor_sync(0xffffffffu, sum, s);
        if (lane == 0) swr[wid] = sum;
        __syncthreads();
        float tot = swr[0];
#pragma unroll
        for (int j = 1; j < 8; j++) tot += swr[j];
        __syncthreads();
        g_p[((h * Z + z) * NPT + tid) * NPT + a] = e / tot;
    }
    if (tid < 128) g_aopart[bid * 128 + tid] = 0.0f;
}

// ---------------- Kernel V: value contraction, 16B gathers + mma.sync ----------------
__global__ __launch_bounds__(256, 4) void val_kernel(const float* __restrict__ xyz) {
    __shared__ __align__(16) __half s_A[64 * ASTRIDE];
    __shared__ __align__(16) __half s_B[KPAD * BSTRIDE];
    __shared__ float s_d[256];
    __shared__ float s_p[256];

    const int tid = threadIdx.x;
    const int b = blockIdx.x;
    const int z = blockIdx.y >> 1;
    const int h = blockIdx.y & 1;
    const int slot = b >> 5;

    {
        const __half* src = g_VfF + ((size_t)((h * Z + z) * NPT + b)) * (HD * CH);
        for (int e = tid; e < KPAD * CH; e += 256) {
            int k = e >> 4, i = e & 15;
            s_B[k * BSTRIDE + i] = (k < HD) ? src[i * HD + k] : __half(0);
        }
    }
    {
        float bx = xyz[(z * NPT + b) * 3 + 0];
        float by = xyz[(z * NPT + b) * 3 + 1];
        float bz = xyz[(z * NPT + b) * 3 + 2];
        float dx = bx - xyz[(z * NPT + tid) * 3 + 0];
        float dy = by - xyz[(z * NPT + tid) * 3 + 1];
        float dz = bz - xyz[(z * NPT + tid) * 3 + 2];
        s_d[tid] = sqrtf(dx * dx + dy * dy + dz * dz + 1e-12f);
        s_p[tid] = g_p[((h * Z + z) * NPT + b) * NPT + tid];
    }
    __syncthreads();

    const int w = tid >> 5, l = tid & 31;
    const int rt = w >> 1, nt = w & 1;
    uint32 sAb = (uint32)__cvta_generic_to_shared(s_A);
    uint32 sBb = (uint32)__cvta_generic_to_shared(s_B);

    for (int ch = 0; ch < 4; ch++) {
        const int ach0 = ch * 64;
        {
            const int p = tid >> 2, q = tid & 3;
            const float TSCALE = (float)(NTAB - 1) / DMAX;
            float x = s_d[ach0 + p] * TSCALE;
            int i0 = (int)x;
            if (i0 > NTAB - 2) i0 = NTAB - 2;
            float f = x - (float)i0;
            const __half* vr = g_Vtab + ((size_t)h * NTAB + i0) * VSTR;
            __half* dst = s_A + p * ASTRIDE;
            for (int c = q; c < 14; c += 4) {
                uint4 r0 = *(const uint4*)(vr + 8 * c);
                uint4 r1 = *(const uint4*)(vr + VSTR + 8 * c);
                *(uint4*)(dst + 8 * c) = lerp8h(r0, r1, f);
            }
        }
        __syncthreads();

        {
            float acc[4] = {0.f, 0.f, 0.f, 0.f};
#pragma unroll
            for (int kt = 0; kt < 7; kt++) {
                uint32 bb0, bb1;
                ldsm_x2t(bb0, bb1,
                         sBb + (kt * 16 + (l & 15)) * (BSTRIDE * 2) + nt * 16);
                uint32 a0, a1, a2, a3;
                ldsm_x4(a0, a1, a2, a3,
                        sAb + (rt * 16 + (l & 15)) * (ASTRIDE * 2)
                            + kt * 32 + (l >> 4) * 16);
                mma16816(acc, a0, a1, a2, a3, bb0, bb1);
            }
            const int rlo = ach0 + rt * 16 + (l >> 2);
            const int rhi = rlo + 8;
            const int col = nt * 8 + 2 * (l & 3);
            const float plo = s_p[rlo];
            const float phi = s_p[rhi];
            float* blo = g_aopart + slot * ZNC + (z * NPT + rlo) * CH + col;
            float* bhi = g_aopart + slot * ZNC + (z * NPT + rhi) * CH + col;
            atomicAdd(blo + 0, acc[0] * plo);
            atomicAdd(blo + 1, acc[1] * plo);
            atomicAdd(bhi + 0, acc[2] * phi);
            atomicAdd(bhi + 1, acc[3] * phi);
        }
        __syncthreads();
    }
}

// ---------------- Kernel C1: sum aopart + CfF projection (fp16 out); zero outpart ----------------
__global__ __launch_bounds__(256) void cff_kernel(const float* __restrict__ Cf) {
    const int bx = blockIdx.x;
    const int z = bx >> 7;
    const int b0 = ((bx >> 2) & 31) * 8;
    const int sl = bx & 3;
    const int tid = threadIdx.x;
    __shared__ float ao[8 * CH];
    if (tid < 8 * CH) {
        const int off = (z * NPT + b0) * CH + tid;
        float acc = 0.f;
#pragma unroll
        for (int s = 0; s < NSLOT; s++) acc += g_aopart[s * ZNC + off];
        ao[tid] = acc;
    }
    g_outpart[bx * 256 + tid] = 0.0f;
    __syncthreads();
    for (int e = tid; e < 25 * CH; e += 256) {
        const int i = e / 25, mm = e - i * 25;
        const int m = sl * 25 + mm;
        const int r = i * HD + m;
        const float* cp = Cf + m * (CH * CH) + i * CH;
        float4 c0 = *(const float4*)(cp);
        float4 c1 = *(const float4*)(cp + 4);
        float4 c2 = *(const float4*)(cp + 8);
        float4 c3 = *(const float4*)(cp + 12);
#pragma unroll
        for (int bl = 0; bl < 8; bl++) {
            const float* f = ao + bl * CH;
            float acc = c0.x*f[0]+c0.y*f[1]+c0.z*f[2]+c0.w*f[3]
                      + c1.x*f[4]+c1.y*f[5]+c1.z*f[6]+c1.w*f[7]
                      + c2.x*f[8]+c2.y*f[9]+c2.z*f[10]+c2.w*f[11]
                      + c3.x*f[12]+c3.y*f[13]+c3.z*f[14]+c3.w*f[15];
            g_CfF[(z * NPT + b0 + bl) * (HD * CH) + r] = __float2half(acc);
        }
    }
}

// ---------------- Kernel C2: final conv, 16B gathers + mma.sync ----------------
__global__ __launch_bounds__(256, 4) void conv_kernel(const float* __restrict__ xyz) {
    __shared__ __align__(16) __half s_A[64 * ASTRIDE];
    __shared__ __align__(16) __half s_B[KPAD * BSTRIDE];
    __shared__ float s_d[256];

    const int tid = threadIdx.x;
    const int b = blockIdx.x;
    const int z = blockIdx.y;
    const int slot = b >> 5;

    {
        const __half* src = g_CfF + ((size_t)(z * NPT + b)) * (HD * CH);
        for (int e = tid; e < KPAD * CH; e += 256) {
            int k = e >> 4, i = e & 15;
            s_B[k * BSTRIDE + i] = (k < HD) ? src[i * HD + k] : __half(0);
        }
    }
    {
        float bx = xyz[(z * NPT + b) * 3 + 0];
        float by = xyz[(z * NPT + b) * 3 + 1];
        float bz = xyz[(z * NPT + b) * 3 + 2];
        float dx = bx - xyz[(z * NPT + tid) * 3 + 0];
        float dy = by - xyz[(z * NPT + tid) * 3 + 1];
        float dz = bz - xyz[(z * NPT + tid) * 3 + 2];
        s_d[tid] = sqrtf(dx * dx + dy * dy + dz * dz + 1e-12f);
    }
    __syncthreads();

    const int w = tid >> 5, l = tid & 31;
    const int rt = w >> 1, nt = w & 1;
    uint32 sAb = (uint32)__cvta_generic_to_shared(s_A);
    uint32 sBb = (uint32)__cvta_generic_to_shared(s_B);

    for (int ch = 0; ch < 4; ch++) {
        const int ach0 = ch * 64;
        {
            const int p = tid >> 2, q = tid & 3;
            const float TSCALE = (float)(NTAB - 1) / DMAX;
            float x = s_d[ach0 + p] * TSCALE;
            int i0 = (int)x;
            if (i0 > NTAB - 2) i0 = NTAB - 2;
            float f = x - (float)i0;
            const __half* cr = g_Ctab + (size_t)i0 * VSTR;
            __half* dst = s_A + p * ASTRIDE;
            for (int c = q; c < 14; c += 4) {
                uint4 r0 = *(const uint4*)(cr + 8 * c);
                uint4 r1 = *(const uint4*)(cr + VSTR + 8 * c);
                *(uint4*)(dst + 8 * c) = lerp8h(r0, r1, f);
            }
        }
        __syncthreads();

        {
            float acc[4] = {0.f, 0.f, 0.f, 0.f};
#pragma unroll
            for (int kt = 0; kt < 7; kt++) {
                uint32 bb0, bb1;
                ldsm_x2t(bb0, bb1,
                         sBb + (kt * 16 + (l & 15)) * (BSTRIDE * 2) + nt * 16);
                uint32 a0, a1, a2, a3;
                ldsm_x4(a0, a1, a2, a3,
                        sAb + (rt * 16 + (l & 15)) * (ASTRIDE * 2)
                            + kt * 32 + (l >> 4) * 16);
                mma16816(acc, a0, a1, a2, a3, bb0, bb1);
            }
            const int rlo = ach0 + rt * 16 + (l >> 2);
            const int rhi = rlo + 8;
            const int col = nt * 8 + 2 * (l & 3);
            float* blo = g_outpart + slot * ZNC + (z * NPT + rlo) * CH + col;
            float* bhi = g_outpart + slot * ZNC + (z * NPT + rhi) * CH + col;
            atomicAdd(blo + 0, acc[0]);
            atomicAdd(blo + 1, acc[1]);
            atomicAdd(bhi + 0, acc[2]);
            atomicAdd(bhi + 1, acc[3]);
        }
        __syncthreads();
    }
}

// ---------------- Kernel F: finalize out ----------------
__global__ __launch_bounds__(256) void final_kernel(float* __restrict__ out) {
    const int e = blockIdx.x * 256 + threadIdx.x;
    if (e < ZNC) {
        float acc = 0.f;
#pragma unroll
        for (int s = 0; s < NSLOT; s++) acc += g_outpart[s * ZNC + e];
        out[e] = acc;
    }
}

// ---------------- launch ----------------
extern "C" void kernel_launch(void* const* d_in, const int* in_sizes, int n_in,
                              void* d_out, int out_size) {
    const float* features = (const float*)d_in[0];
    const float* xyz = (const float*)d_in[1];
    const float* Wq = (const float*)d_in[2];
    const float* K0 = (const float*)d_in[3];
    const float* K1 = (const float*)d_in[4];
    const float* Kf = (const float*)d_in[5];
    const float* V0 = (const float*)d_in[6];
    const float* Vf = (const float*)d_in[7];
    const float* C0 = (const float*)d_in[8];
    const float* C1 = (const float*)d_in[9];
    const float* Cf = (const float*)d_in[10];
    float* out = (float*)d_out;

    cudaFuncSetAttribute(build_kernel, cudaFuncAttributeMaxDynamicSharedMemorySize,
                         B_SMEM_FLOATS * (int)sizeof(float));

    build_kernel<<<296, 256, B_SMEM_FLOATS * sizeof(float)>>>(
        features, Wq, Kf, Vf, K0, K1, C0, C1, V0);
    pair_kernel<<<dim3(NPT, Z * HEADS), 256>>>(xyz);
    softmax_p_kernel<<<Z * NPT, 256>>>();
    val_kernel<<<dim3(NPT, Z * HEADS), 256>>>(xyz);
    cff_kernel<<<256, 256>>>(Cf);
    conv_kernel<<<dim3(NPT, Z), 256>>>(xyz);
    final_kernel<<<(ZNC + 255) / 256, 256>>>(out);
}